// round 1
// baseline (speedup 1.0000x reference)
#include <cuda_runtime.h>
#include <cstdint>

// Problem constants
#define PIX 16384        // B*H*W
#define NSEQ 4096        // H*W
#define BSZ 4
#define CH 128

// ---------------- scratch (device globals; no allocation allowed) -------------
__device__ float g_x4[PIX * 4];
__device__ float g_x2[PIX * 2];
__device__ float g_neigh[PIX * 256];
__device__ float g_keycat[PIX * 256];
__device__ float g_valcat[PIX * 256];
__device__ float g_keyn[PIX * 128];
__device__ float g_valn[PIX * 128];
__device__ float g_nowf[PIX * 128];
__device__ float g_nowkey[PIX * 128];
__device__ float g_nowval[PIX * 128];
__device__ float g_q[PIX * 128];
__device__ float g_k[PIX * 128];
__device__ float g_v[PIX * 128];

// ---------------- gather: split event planes into [pixel][chan] rows ----------
__global__ void __launch_bounds__(256) gather_kernel(const float* __restrict__ event,
                                                     float* __restrict__ x4,
                                                     float* __restrict__ x2) {
    int p = blockIdx.x * blockDim.x + threadIdx.x;
    if (p >= PIX) return;
    int b = p >> 12;
    int hw = p & 4095;
    const float* e = event + (size_t)b * 6 * NSEQ;
    // pro = ch 0:2, now = ch 2:4, lat = ch 4:6 ; x4 = [pro|lat], x2 = now
    x4[p * 4 + 0] = e[0 * NSEQ + hw];
    x4[p * 4 + 1] = e[1 * NSEQ + hw];
    x4[p * 4 + 2] = e[4 * NSEQ + hw];
    x4[p * 4 + 3] = e[5 * NSEQ + hw];
    x2[p * 2 + 0] = e[2 * NSEQ + hw];
    x2[p * 2 + 1] = e[3 * NSEQ + hw];
}

// ---------------- generic relu-GEMM: out[m][n] = relu(sum_k in[m][k]*w[n][k]+b[n])
// block: 256 threads, 64x64 tile, 4x4 per thread, K staged in chunks of 16
__global__ void __launch_bounds__(256) gemm_relu(
    const float* __restrict__ in, int in_ld,
    const float* __restrict__ w,
    const float* __restrict__ bias,
    float* __restrict__ out, int out_ld,
    int Cin) {
    __shared__ float As[16][65];
    __shared__ float Bs[16][65];
    const int tid = threadIdx.x;
    const int tx = tid & 15, ty = tid >> 4;
    const int m0 = blockIdx.x * 64;
    const int n0 = blockIdx.y * 64;
    float acc[4][4] = {};

    for (int k0 = 0; k0 < Cin; k0 += 16) {
        int kc = Cin - k0;
        if (kc > 16) kc = 16;
        for (int i = tid; i < 64 * 16; i += 256) {
            int r = i >> 4, k = i & 15;
            As[k][r] = (k < kc) ? in[(size_t)(m0 + r) * in_ld + k0 + k] : 0.f;
            Bs[k][r] = (k < kc) ? w[(size_t)(n0 + r) * Cin + k0 + k] : 0.f;
        }
        __syncthreads();
#pragma unroll
        for (int k = 0; k < 16; k++) {
            float a[4], bb[4];
#pragma unroll
            for (int i = 0; i < 4; i++) a[i] = As[k][ty * 4 + i];
#pragma unroll
            for (int j = 0; j < 4; j++) bb[j] = Bs[k][tx * 4 + j];
#pragma unroll
            for (int i = 0; i < 4; i++)
#pragma unroll
                for (int j = 0; j < 4; j++)
                    acc[i][j] = fmaf(a[i], bb[j], acc[i][j]);
        }
        __syncthreads();
    }
#pragma unroll
    for (int j = 0; j < 4; j++) {
        float bj = bias[n0 + tx * 4 + j];
#pragma unroll
        for (int i = 0; i < 4; i++) {
            float r = acc[i][j] + bj;
            out[(size_t)(m0 + ty * 4 + i) * out_ld + n0 + tx * 4 + j] = r > 0.f ? r : 0.f;
        }
    }
}

// ---------------- fast exp (Schraudolph). x <= 0 in softmax use; clamp avoids wrap.
// Relative error ~3% — fine: attention path is damped by THITA=1e-4 in the output.
__device__ __forceinline__ float fast_exp(float x) {
    x = fmaxf(x, -80.f);
    int i = (int)(fmaf(x, 12102203.0f, 1064866805.0f));
    return __int_as_float(i);
}

// ---------------- flash attention, fp32, BM=BN=64, D=128 ---------------------
// grid (NSEQ/64, BSZ), 256 threads. smem: Q,K,V tiles (float4, XOR-swizzled) + P.
// Epilogue writes out[b][c][n] = 1e-4 * O/l + now_val.
#define ATTN_SMEM ((3 * 64 * 32 * 16) + (64 * 64 * 4))  // 114688 B

__global__ void __launch_bounds__(256) attn_kernel(
    const float* __restrict__ gq,
    const float* __restrict__ gk,
    const float* __restrict__ gv,
    const float* __restrict__ gnv,
    float* __restrict__ out) {
    extern __shared__ float sm[];
    float4* Qs = (float4*)sm;          // [64][32] float4 (swizzled)
    float4* Ks = Qs + 64 * 32;
    float4* Vs = Ks + 64 * 32;
    float* Ps = (float*)(Vs + 64 * 32);  // [64][64]

    const int tid = threadIdx.x;
    const int tx = tid & 15, ty = tid >> 4;
    const int b = blockIdx.y;
    const int q0 = blockIdx.x * 64;

    const float4* Qg = (const float4*)(gq + (size_t)(b * NSEQ + q0) * CH);
    const float4* Kg = (const float4*)(gk + (size_t)b * NSEQ * CH);
    const float4* Vg = (const float4*)(gv + (size_t)b * NSEQ * CH);

    // load Q tile (2048 float4, swizzle: group g of row r stored at g ^ ((r>>2)&7))
    for (int i = tid; i < 64 * 32; i += 256) {
        int r = i >> 5, g = i & 31;
        Qs[r * 32 + (g ^ ((r >> 2) & 7))] = Qg[i];
    }

    float o[4][8];
#pragma unroll
    for (int i = 0; i < 4; i++)
#pragma unroll
        for (int j = 0; j < 8; j++) o[i][j] = 0.f;
    float mrow[4], lrow[4];
#pragma unroll
    for (int i = 0; i < 4; i++) { mrow[i] = -1e30f; lrow[i] = 0.f; }

    for (int j0 = 0; j0 < NSEQ; j0 += 64) {
        __syncthreads();  // protect Ks/Vs/Ps reuse (also covers initial Q load)
        for (int i = tid; i < 64 * 32; i += 256) {
            int r = i >> 5, g = i & 31;
            int sg = g ^ ((r >> 2) & 7);
            Ks[r * 32 + sg] = Kg[(size_t)j0 * 32 + i];
            Vs[r * 32 + sg] = Vg[(size_t)j0 * 32 + i];
        }
        __syncthreads();

        // S tile: rows ty*4.., cols tx*4..
        float s[4][4] = {};
#pragma unroll 4
        for (int kk = 0; kk < 32; kk++) {
            float4 a[4], bb[4];
#pragma unroll
            for (int i = 0; i < 4; i++) {
                int r = ty * 4 + i;
                a[i] = Qs[r * 32 + (kk ^ ((r >> 2) & 7))];
            }
#pragma unroll
            for (int j = 0; j < 4; j++) {
                int r = tx * 4 + j;
                bb[j] = Ks[r * 32 + (kk ^ ((r >> 2) & 7))];
            }
#pragma unroll
            for (int i = 0; i < 4; i++)
#pragma unroll
                for (int j = 0; j < 4; j++) {
                    s[i][j] = fmaf(a[i].x, bb[j].x, s[i][j]);
                    s[i][j] = fmaf(a[i].y, bb[j].y, s[i][j]);
                    s[i][j] = fmaf(a[i].z, bb[j].z, s[i][j]);
                    s[i][j] = fmaf(a[i].w, bb[j].w, s[i][j]);
                }
        }

        // online softmax: reduce across tx (lane bits 0..3)
        float scl[4];
#pragma unroll
        for (int i = 0; i < 4; i++) {
            float v = fmaxf(fmaxf(s[i][0], s[i][1]), fmaxf(s[i][2], s[i][3]));
            v = fmaxf(v, __shfl_xor_sync(0xffffffffu, v, 1));
            v = fmaxf(v, __shfl_xor_sync(0xffffffffu, v, 2));
            v = fmaxf(v, __shfl_xor_sync(0xffffffffu, v, 4));
            v = fmaxf(v, __shfl_xor_sync(0xffffffffu, v, 8));
            float mnew = fmaxf(mrow[i], v);
            scl[i] = fast_exp(mrow[i] - mnew);
            mrow[i] = mnew;
        }
#pragma unroll
        for (int i = 0; i < 4; i++) {
            float4 pv;
            pv.x = fast_exp(s[i][0] - mrow[i]);
            pv.y = fast_exp(s[i][1] - mrow[i]);
            pv.z = fast_exp(s[i][2] - mrow[i]);
            pv.w = fast_exp(s[i][3] - mrow[i]);
            ((float4*)(Ps + (ty * 4 + i) * 64))[tx] = pv;
            float rs = pv.x + pv.y + pv.z + pv.w;
            rs += __shfl_xor_sync(0xffffffffu, rs, 1);
            rs += __shfl_xor_sync(0xffffffffu, rs, 2);
            rs += __shfl_xor_sync(0xffffffffu, rs, 4);
            rs += __shfl_xor_sync(0xffffffffu, rs, 8);
            lrow[i] = lrow[i] * scl[i] + rs;
#pragma unroll
            for (int j = 0; j < 8; j++) o[i][j] *= scl[i];
        }
        __syncthreads();  // P visible

        // O += P * V ; thread cols = tx*8..tx*8+7 (2 swizzled float4 groups)
#pragma unroll 4
        for (int m = 0; m < 64; m++) {
            int sw = (m >> 2) & 7;
            float4 v0 = Vs[m * 32 + ((tx * 2) ^ sw)];
            float4 v1 = Vs[m * 32 + ((tx * 2 + 1) ^ sw)];
#pragma unroll
            for (int i = 0; i < 4; i++) {
                float p = Ps[(ty * 4 + i) * 64 + m];
                o[i][0] = fmaf(p, v0.x, o[i][0]);
                o[i][1] = fmaf(p, v0.y, o[i][1]);
                o[i][2] = fmaf(p, v0.z, o[i][2]);
                o[i][3] = fmaf(p, v0.w, o[i][3]);
                o[i][4] = fmaf(p, v1.x, o[i][4]);
                o[i][5] = fmaf(p, v1.y, o[i][5]);
                o[i][6] = fmaf(p, v1.z, o[i][6]);
                o[i][7] = fmaf(p, v1.w, o[i][7]);
            }
        }
    }

    // epilogue: out[b][c][n] = THITA * o/l + now_val[b][c][n]
    const float* nv = gnv + (size_t)(b * NSEQ + q0) * CH;
    float* ob = out + (size_t)b * CH * NSEQ;
#pragma unroll
    for (int i = 0; i < 4; i++) {
        int n = q0 + ty * 4 + i;
        float inv = 1.f / lrow[i];
#pragma unroll
        for (int j = 0; j < 8; j++) {
            int c = tx * 8 + j;
            float val = fmaf(1e-4f, o[i][j] * inv, nv[(ty * 4 + i) * CH + c]);
            ob[(size_t)c * NSEQ + n] = val;
        }
    }
}

// ---------------- host launch --------------------------------------------------
extern "C" void kernel_launch(void* const* d_in, const int* in_sizes, int n_in,
                              void* d_out, int out_size) {
    const float* event = (const float*)d_in[0];
    const float* W[12];
    const float* Bv[12];
    for (int i = 0; i < 12; i++) {
        W[i] = (const float*)d_in[1 + 2 * i];
        Bv[i] = (const float*)d_in[2 + 2 * i];
    }
    // 0 neighbor, 1 pro_key, 2 pro_val, 3 lat_key, 4 lat_val, 5 tmp1,
    // 6 now1, 7 now_key, 8 now_val, 9 q, 10 k, 11 v

    float *x4, *x2, *neigh, *keycat, *valcat, *keyn, *valn, *nowf, *nowkey, *nowval, *q, *k, *v;
    cudaGetSymbolAddress((void**)&x4, g_x4);
    cudaGetSymbolAddress((void**)&x2, g_x2);
    cudaGetSymbolAddress((void**)&neigh, g_neigh);
    cudaGetSymbolAddress((void**)&keycat, g_keycat);
    cudaGetSymbolAddress((void**)&valcat, g_valcat);
    cudaGetSymbolAddress((void**)&keyn, g_keyn);
    cudaGetSymbolAddress((void**)&valn, g_valn);
    cudaGetSymbolAddress((void**)&nowf, g_nowf);
    cudaGetSymbolAddress((void**)&nowkey, g_nowkey);
    cudaGetSymbolAddress((void**)&nowval, g_nowval);
    cudaGetSymbolAddress((void**)&q, g_q);
    cudaGetSymbolAddress((void**)&k, g_k);
    cudaGetSymbolAddress((void**)&v, g_v);

    cudaFuncSetAttribute(attn_kernel, cudaFuncAttributeMaxDynamicSharedMemorySize, ATTN_SMEM);

    dim3 g1(PIX / 64, 2);  // Cout = 128
    dim3 g2(PIX / 64, 4);  // Cout = 256

    gather_kernel<<<PIX / 256, 256>>>(event, x4, x2);

    gemm_relu<<<g2, 256>>>(x4, 4, W[0], Bv[0], neigh, 256, 4);              // neighbor
    gemm_relu<<<g1, 256>>>(neigh, 256, W[1], Bv[1], keycat, 256, 128);      // pro_key -> keycat[:,0:128]
    gemm_relu<<<g1, 256>>>(neigh, 256, W[3], Bv[3], keycat + 128, 256, 128);// lat_key -> keycat[:,128:]
    gemm_relu<<<g1, 256>>>(neigh + 128, 256, W[2], Bv[2], valcat, 256, 128);// pro_val
    gemm_relu<<<g1, 256>>>(neigh + 128, 256, W[4], Bv[4], valcat + 128, 256, 128); // lat_val
    gemm_relu<<<g1, 256>>>(keycat, 256, W[5], Bv[5], keyn, 128, 256);       // key_n = tmp1(keycat)
    gemm_relu<<<g1, 256>>>(valcat, 256, W[5], Bv[5], valn, 128, 256);       // val_n = tmp1(valcat)
    gemm_relu<<<g1, 256>>>(x2, 2, W[6], Bv[6], nowf, 128, 2);               // now_f
    gemm_relu<<<g1, 256>>>(nowf, 128, W[7], Bv[7], nowkey, 128, 128);       // now_key
    gemm_relu<<<g1, 256>>>(nowf, 128, W[8], Bv[8], nowval, 128, 128);       // now_val
    gemm_relu<<<g1, 256>>>(keyn, 128, W[9], Bv[9], q, 128, 128);            // q
    gemm_relu<<<g1, 256>>>(nowkey, 128, W[10], Bv[10], k, 128, 128);        // k
    gemm_relu<<<g1, 256>>>(valn, 128, W[11], Bv[11], v, 128, 128);          // v

    attn_kernel<<<dim3(NSEQ / 64, BSZ), 256, ATTN_SMEM>>>(q, k, v, nowval, (float*)d_out);
}

// round 2
// speedup vs baseline: 2.8632x; 2.8632x over previous
#include <cuda_runtime.h>
#include <cuda_bf16.h>
#include <cstdint>

// Problem constants
#define PIX 16384        // B*H*W
#define NSEQ 4096        // H*W
#define BSZ 4
#define CH 128
#define THITA 1e-4f

// ---------------- scratch (device globals; no allocation allowed) -------------
__device__ float g_x4[PIX * 4];
__device__ float g_x2[PIX * 2];
__device__ float g_neigh[PIX * 256];
__device__ float g_keycat[PIX * 256];
__device__ float g_valcat[PIX * 256];
__device__ float g_keyn[PIX * 128];
__device__ float g_valn[PIX * 128];
__device__ float g_nowf[PIX * 128];
__device__ float g_nowkv[PIX * 256];   // [now_key | now_val]
__device__ __nv_bfloat16 g_qb[PIX * 128];
__device__ __nv_bfloat16 g_kb[PIX * 128];
__device__ __nv_bfloat16 g_vb[PIX * 128];
__device__ float g_wcat1[256 * 128];   // [w_pro_key ; w_lat_key]
__device__ float g_wcat2[256 * 128];   // [w_pro_val ; w_lat_val]
__device__ float g_wcat3[256 * 128];   // [w_now_key ; w_now_val]
__device__ float g_bcat1[256];
__device__ float g_bcat2[256];
__device__ float g_bcat3[256];

// ---------------- gather: split event planes into [pixel][chan] rows ----------
__global__ void __launch_bounds__(256) gather_kernel(const float* __restrict__ event,
                                                     float* __restrict__ x4,
                                                     float* __restrict__ x2) {
    int p = blockIdx.x * blockDim.x + threadIdx.x;
    if (p >= PIX) return;
    int b = p >> 12;
    int hw = p & 4095;
    const float* e = event + (size_t)b * 6 * NSEQ;
    x4[p * 4 + 0] = e[0 * NSEQ + hw];
    x4[p * 4 + 1] = e[1 * NSEQ + hw];
    x4[p * 4 + 2] = e[4 * NSEQ + hw];
    x4[p * 4 + 3] = e[5 * NSEQ + hw];
    x2[p * 2 + 0] = e[2 * NSEQ + hw];
    x2[p * 2 + 1] = e[3 * NSEQ + hw];
}

// ---------------- weight concatenation (one launch, graph-capturable) --------
__global__ void __launch_bounds__(256) concat_w_kernel(
    const float* __restrict__ wpk, const float* __restrict__ wlk,
    const float* __restrict__ wpv, const float* __restrict__ wlv,
    const float* __restrict__ wnk, const float* __restrict__ wnv,
    const float* __restrict__ bpk, const float* __restrict__ blk,
    const float* __restrict__ bpv, const float* __restrict__ blv,
    const float* __restrict__ bnk, const float* __restrict__ bnv) {
    int i = blockIdx.x * blockDim.x + threadIdx.x;   // 0..32767
    if (i < 16384) {
        g_wcat1[i] = wpk[i]; g_wcat2[i] = wpv[i]; g_wcat3[i] = wnk[i];
    } else {
        int j = i - 16384;
        g_wcat1[i] = wlk[j]; g_wcat2[i] = wlv[j]; g_wcat3[i] = wnv[j];
    }
    if (i < 128) {
        g_bcat1[i] = bpk[i]; g_bcat2[i] = bpv[i]; g_bcat3[i] = bnk[i];
    } else if (i < 256) {
        int j = i - 128;
        g_bcat1[i] = blk[j]; g_bcat2[i] = blv[j]; g_bcat3[i] = bnv[j];
    }
}

// ---------------- generic relu-GEMM: out[m][n] = relu(sum_k in[m][k]*w[n][k]+b[n])
template <typename OutT>
__global__ void __launch_bounds__(256) gemm_relu(
    const float* __restrict__ in, int in_ld,
    const float* __restrict__ w,
    const float* __restrict__ bias,
    OutT* __restrict__ out, int out_ld,
    int Cin) {
    __shared__ float As[16][65];
    __shared__ float Bs[16][65];
    const int tid = threadIdx.x;
    const int tx = tid & 15, ty = tid >> 4;
    const int m0 = blockIdx.x * 64;
    const int n0 = blockIdx.y * 64;
    float acc[4][4] = {};

    for (int k0 = 0; k0 < Cin; k0 += 16) {
        int kc = Cin - k0;
        if (kc > 16) kc = 16;
        for (int i = tid; i < 64 * 16; i += 256) {
            int r = i >> 4, k = i & 15;
            As[k][r] = (k < kc) ? in[(size_t)(m0 + r) * in_ld + k0 + k] : 0.f;
            Bs[k][r] = (k < kc) ? w[(size_t)(n0 + r) * Cin + k0 + k] : 0.f;
        }
        __syncthreads();
#pragma unroll
        for (int k = 0; k < 16; k++) {
            float a[4], bb[4];
#pragma unroll
            for (int i = 0; i < 4; i++) a[i] = As[k][ty * 4 + i];
#pragma unroll
            for (int j = 0; j < 4; j++) bb[j] = Bs[k][tx * 4 + j];
#pragma unroll
            for (int i = 0; i < 4; i++)
#pragma unroll
                for (int j = 0; j < 4; j++)
                    acc[i][j] = fmaf(a[i], bb[j], acc[i][j]);
        }
        __syncthreads();
    }
#pragma unroll
    for (int j = 0; j < 4; j++) {
        float bj = bias[n0 + tx * 4 + j];
#pragma unroll
        for (int i = 0; i < 4; i++) {
            float r = acc[i][j] + bj;
            r = r > 0.f ? r : 0.f;
            out[(size_t)(m0 + ty * 4 + i) * out_ld + n0 + tx * 4 + j] = (OutT)r;
        }
    }
}

// ---------------- fast exp (Schraudolph); args <= 0, clamp avoids wraparound --
__device__ __forceinline__ float fast_exp(float x) {
    x = fmaxf(x, -80.f);
    int i = (int)(fmaf(x, 12102203.0f, 1064866805.0f));
    return __int_as_float(i);
}

// ---------------- mma / ldmatrix helpers --------------------------------------
__device__ __forceinline__ void mma16816(float* c, const uint32_t* a, const uint32_t* b) {
    asm volatile(
        "mma.sync.aligned.m16n8k16.row.col.f32.bf16.bf16.f32 "
        "{%0,%1,%2,%3}, {%4,%5,%6,%7}, {%8,%9}, {%0,%1,%2,%3};"
        : "+f"(c[0]), "+f"(c[1]), "+f"(c[2]), "+f"(c[3])
        : "r"(a[0]), "r"(a[1]), "r"(a[2]), "r"(a[3]), "r"(b[0]), "r"(b[1]));
}

__device__ __forceinline__ void ldsm4(uint32_t& r0, uint32_t& r1, uint32_t& r2, uint32_t& r3,
                                      const void* p) {
    uint32_t addr = (uint32_t)__cvta_generic_to_shared(p);
    asm volatile("ldmatrix.sync.aligned.m8n8.x4.shared.b16 {%0,%1,%2,%3}, [%4];"
                 : "=r"(r0), "=r"(r1), "=r"(r2), "=r"(r3) : "r"(addr));
}

__device__ __forceinline__ void ldsm4t(uint32_t& r0, uint32_t& r1, uint32_t& r2, uint32_t& r3,
                                       const void* p) {
    uint32_t addr = (uint32_t)__cvta_generic_to_shared(p);
    asm volatile("ldmatrix.sync.aligned.m8n8.x4.trans.shared.b16 {%0,%1,%2,%3}, [%4];"
                 : "=r"(r0), "=r"(r1), "=r"(r2), "=r"(r3) : "r"(addr));
}

__device__ __forceinline__ uint32_t packbf2(float lo, float hi) {
    uint32_t d;
    asm("cvt.rn.bf16x2.f32 %0, %1, %2;" : "=r"(d) : "f"(hi), "f"(lo));
    return d;
}

// ---------------- flash attention, bf16 HMMA, BM=128 BN=64 D=128 --------------
// 256 threads = 8 warps; each warp owns 16 query rows.
// out[b][c][n] = THITA * O[n][c]/l[n] + now_val[n][c]
#define OPITCH 132
#define ATTN_SMEM (128 * OPITCH * 4)   // 67584 >= 2*64*128*2 (K+V bf16)

__global__ void __launch_bounds__(256, 1) attn_kernel(
    const __nv_bfloat16* __restrict__ gq,
    const __nv_bfloat16* __restrict__ gk,
    const __nv_bfloat16* __restrict__ gv,
    const float* __restrict__ gnv, int nv_ld,
    float* __restrict__ out) {
    extern __shared__ char smraw[];
    __nv_bfloat16* Ks = (__nv_bfloat16*)smraw;     // [64][128] swizzled
    __nv_bfloat16* Vs = Ks + 64 * 128;             // [64][128] swizzled
    float* OutS = (float*)smraw;                   // reused post-loop, [128][OPITCH]

    const int tid = threadIdx.x;
    const int lane = tid & 31, w = tid >> 5;
    const int g = lane >> 2, tc = lane & 3;
    const int b = blockIdx.y;
    const int q0 = blockIdx.x * 128;

    // ---- load Q fragments (once, straight from bf16 global) ----
    uint32_t qa[8][4];
    {
        const __nv_bfloat16* Qb = gq + ((size_t)(b * NSEQ) + q0 + w * 16) * CH;
#pragma unroll
        for (int kb = 0; kb < 8; kb++) {
            qa[kb][0] = *(const uint32_t*)(Qb + (size_t)g * CH + kb * 16 + 2 * tc);
            qa[kb][1] = *(const uint32_t*)(Qb + (size_t)(g + 8) * CH + kb * 16 + 2 * tc);
            qa[kb][2] = *(const uint32_t*)(Qb + (size_t)g * CH + kb * 16 + 8 + 2 * tc);
            qa[kb][3] = *(const uint32_t*)(Qb + (size_t)(g + 8) * CH + kb * 16 + 8 + 2 * tc);
        }
    }

    float O[16][4];
#pragma unroll
    for (int i = 0; i < 16; i++)
#pragma unroll
        for (int j = 0; j < 4; j++) O[i][j] = 0.f;
    float mrow0 = -1e30f, mrow1 = -1e30f, lrow0 = 0.f, lrow1 = 0.f;

    // precomputed per-thread ldmatrix row/chunk components
    const int rK_loc = ((lane >> 4) & 1) * 8 + (lane & 7);
    const int cK_bit = (lane >> 3) & 1;
    const int rV_loc = ((lane >> 3) & 1) * 8 + (lane & 7);
    const int cV_bit = lane >> 4;

    const __nv_bfloat16* Kgb = gk + (size_t)b * NSEQ * CH;
    const __nv_bfloat16* Vgb = gv + (size_t)b * NSEQ * CH;

    for (int jt = 0; jt < NSEQ / 64; jt++) {
        __syncthreads();
        // stage K,V tile (bf16, 16B-chunk XOR swizzle)
        {
            const uint4* Kg = (const uint4*)(Kgb + (size_t)jt * 64 * CH);
            const uint4* Vg = (const uint4*)(Vgb + (size_t)jt * 64 * CH);
#pragma unroll
            for (int i = tid; i < 1024; i += 256) {
                int r = i >> 4, ch = i & 15;
                int sch = ch ^ (r & 7);
                ((uint4*)Ks)[r * 16 + sch] = Kg[i];
                ((uint4*)Vs)[r * 16 + sch] = Vg[i];
            }
        }
        __syncthreads();

        // ---- S = Q K^T  (16x64 per warp) ----
        float S[8][4];
#pragma unroll
        for (int i = 0; i < 8; i++)
#pragma unroll
            for (int j = 0; j < 4; j++) S[i][j] = 0.f;
#pragma unroll
        for (int kb = 0; kb < 8; kb++) {
#pragma unroll
            for (int p = 0; p < 4; p++) {
                int r = p * 16 + rK_loc;
                int ch = 2 * kb + cK_bit;
                uint32_t b0, b1, b2, b3;
                ldsm4(b0, b1, b2, b3, Ks + r * 128 + ((ch ^ (r & 7)) << 3));
                uint32_t bb[2] = {b0, b1};
                mma16816(S[2 * p], qa[kb], bb);
                uint32_t bb2[2] = {b2, b3};
                mma16816(S[2 * p + 1], qa[kb], bb2);
            }
        }

        // ---- online softmax (rows g and g+8) ----
        float m0 = -1e30f, m1 = -1e30f;
#pragma unroll
        for (int nb = 0; nb < 8; nb++) {
            m0 = fmaxf(m0, fmaxf(S[nb][0], S[nb][1]));
            m1 = fmaxf(m1, fmaxf(S[nb][2], S[nb][3]));
        }
        m0 = fmaxf(m0, __shfl_xor_sync(0xffffffffu, m0, 1));
        m0 = fmaxf(m0, __shfl_xor_sync(0xffffffffu, m0, 2));
        m1 = fmaxf(m1, __shfl_xor_sync(0xffffffffu, m1, 1));
        m1 = fmaxf(m1, __shfl_xor_sync(0xffffffffu, m1, 2));
        float mn0 = fmaxf(mrow0, m0), mn1 = fmaxf(mrow1, m1);
        float scl0 = fast_exp(mrow0 - mn0), scl1 = fast_exp(mrow1 - mn1);
        mrow0 = mn0; mrow1 = mn1;
        float rs0 = 0.f, rs1 = 0.f;
#pragma unroll
        for (int nb = 0; nb < 8; nb++) {
            S[nb][0] = fast_exp(S[nb][0] - mn0);
            S[nb][1] = fast_exp(S[nb][1] - mn0);
            S[nb][2] = fast_exp(S[nb][2] - mn1);
            S[nb][3] = fast_exp(S[nb][3] - mn1);
            rs0 += S[nb][0] + S[nb][1];
            rs1 += S[nb][2] + S[nb][3];
        }
        rs0 += __shfl_xor_sync(0xffffffffu, rs0, 1);
        rs0 += __shfl_xor_sync(0xffffffffu, rs0, 2);
        rs1 += __shfl_xor_sync(0xffffffffu, rs1, 1);
        rs1 += __shfl_xor_sync(0xffffffffu, rs1, 2);
        lrow0 = lrow0 * scl0 + rs0;
        lrow1 = lrow1 * scl1 + rs1;
#pragma unroll
        for (int nb = 0; nb < 16; nb++) {
            O[nb][0] *= scl0; O[nb][1] *= scl0;
            O[nb][2] *= scl1; O[nb][3] *= scl1;
        }

        // ---- P fragments from S accumulators (C->A layout identity) ----
        uint32_t pa[4][4];
#pragma unroll
        for (int jb = 0; jb < 4; jb++) {
            pa[jb][0] = packbf2(S[2 * jb][0], S[2 * jb][1]);
            pa[jb][1] = packbf2(S[2 * jb][2], S[2 * jb][3]);
            pa[jb][2] = packbf2(S[2 * jb + 1][0], S[2 * jb + 1][1]);
            pa[jb][3] = packbf2(S[2 * jb + 1][2], S[2 * jb + 1][3]);
        }

        // ---- O += P V ----
#pragma unroll
        for (int jb = 0; jb < 4; jb++) {
            int r = jb * 16 + rV_loc;
#pragma unroll
            for (int cp = 0; cp < 8; cp++) {
                int ch = 2 * cp + cV_bit;
                uint32_t b0, b1, b2, b3;
                ldsm4t(b0, b1, b2, b3, Vs + r * 128 + ((ch ^ (r & 7)) << 3));
                uint32_t bb[2] = {b0, b1};
                mma16816(O[2 * cp], pa[jb], bb);
                uint32_t bb2[2] = {b2, b3};
                mma16816(O[2 * cp + 1], pa[jb], bb2);
            }
        }
    }

    // ---- epilogue: stage out[c][n] patch in smem, coalesced global write ----
    __syncthreads();   // everyone done reading Ks/Vs
    {
        float inv0 = 1.f / lrow0, inv1 = 1.f / lrow1;
        int row0 = w * 16 + g, row1 = row0 + 8;
        const float* nvp0 = gnv + ((size_t)(b * NSEQ) + q0 + row0) * nv_ld;
        const float* nvp1 = gnv + ((size_t)(b * NSEQ) + q0 + row1) * nv_ld;
#pragma unroll
        for (int nb = 0; nb < 16; nb++) {
            int c = nb * 8 + 2 * tc;
            float2 nv0 = *(const float2*)(nvp0 + c);
            float2 nv1 = *(const float2*)(nvp1 + c);
            OutS[c * OPITCH + row0] = fmaf(THITA, O[nb][0] * inv0, nv0.x);
            OutS[(c + 1) * OPITCH + row0] = fmaf(THITA, O[nb][1] * inv0, nv0.y);
            OutS[c * OPITCH + row1] = fmaf(THITA, O[nb][2] * inv1, nv1.x);
            OutS[(c + 1) * OPITCH + row1] = fmaf(THITA, O[nb][3] * inv1, nv1.y);
        }
    }
    __syncthreads();
    {
        float* ob = out + (size_t)b * CH * NSEQ + q0;
        for (int i = tid; i < 128 * 128 / 4; i += 256) {
            int idx = i * 4;
            int c = idx >> 7, nl = idx & 127;
            float4 v = *(const float4*)(OutS + c * OPITCH + nl);
            *(float4*)(ob + (size_t)c * NSEQ + nl) = v;
        }
    }
}

// ---------------- host launch --------------------------------------------------
extern "C" void kernel_launch(void* const* d_in, const int* in_sizes, int n_in,
                              void* d_out, int out_size) {
    const float* event = (const float*)d_in[0];
    const float* W[12];
    const float* Bv[12];
    for (int i = 0; i < 12; i++) {
        W[i] = (const float*)d_in[1 + 2 * i];
        Bv[i] = (const float*)d_in[2 + 2 * i];
    }
    // 0 neighbor, 1 pro_key, 2 pro_val, 3 lat_key, 4 lat_val, 5 tmp1,
    // 6 now1, 7 now_key, 8 now_val, 9 q, 10 k, 11 v

    float *x4, *x2, *neigh, *keycat, *valcat, *keyn, *valn, *nowf, *nowkv;
    float *wc1, *wc2, *wc3, *bc1, *bc2, *bc3;
    __nv_bfloat16 *qb, *kb, *vb;
    cudaGetSymbolAddress((void**)&x4, g_x4);
    cudaGetSymbolAddress((void**)&x2, g_x2);
    cudaGetSymbolAddress((void**)&neigh, g_neigh);
    cudaGetSymbolAddress((void**)&keycat, g_keycat);
    cudaGetSymbolAddress((void**)&valcat, g_valcat);
    cudaGetSymbolAddress((void**)&keyn, g_keyn);
    cudaGetSymbolAddress((void**)&valn, g_valn);
    cudaGetSymbolAddress((void**)&nowf, g_nowf);
    cudaGetSymbolAddress((void**)&nowkv, g_nowkv);
    cudaGetSymbolAddress((void**)&qb, g_qb);
    cudaGetSymbolAddress((void**)&kb, g_kb);
    cudaGetSymbolAddress((void**)&vb, g_vb);
    cudaGetSymbolAddress((void**)&wc1, g_wcat1);
    cudaGetSymbolAddress((void**)&wc2, g_wcat2);
    cudaGetSymbolAddress((void**)&wc3, g_wcat3);
    cudaGetSymbolAddress((void**)&bc1, g_bcat1);
    cudaGetSymbolAddress((void**)&bc2, g_bcat2);
    cudaGetSymbolAddress((void**)&bc3, g_bcat3);

    cudaFuncSetAttribute(attn_kernel, cudaFuncAttributeMaxDynamicSharedMemorySize, ATTN_SMEM);

    dim3 g128(PIX / 64, 2);   // N = 128
    dim3 g256(PIX / 64, 4);   // N = 256

    gather_kernel<<<PIX / 256, 256>>>(event, x4, x2);
    concat_w_kernel<<<128, 256>>>(W[1], W[3], W[2], W[4], W[7], W[8],
                                  Bv[1], Bv[3], Bv[2], Bv[4], Bv[7], Bv[8]);

    // conv chain
    gemm_relu<float><<<g256, 256>>>(x4, 4, W[0], Bv[0], neigh, 256, 4);         // neighbor
    gemm_relu<float><<<g256, 256>>>(neigh, 256, wc1, bc1, keycat, 256, 128);    // [pro_key|lat_key]
    gemm_relu<float><<<g256, 256>>>(neigh + 128, 256, wc2, bc2, valcat, 256, 128); // [pro_val|lat_val]
    gemm_relu<float><<<g128, 256>>>(keycat, 256, W[5], Bv[5], keyn, 128, 256);  // key_n
    gemm_relu<float><<<g128, 256>>>(valcat, 256, W[5], Bv[5], valn, 128, 256);  // val_n
    gemm_relu<float><<<g128, 256>>>(x2, 2, W[6], Bv[6], nowf, 128, 2);          // now_f
    gemm_relu<float><<<g256, 256>>>(nowf, 128, wc3, bc3, nowkv, 256, 128);      // [now_key|now_val]
    gemm_relu<__nv_bfloat16><<<g128, 256>>>(keyn, 128, W[9], Bv[9], qb, 128, 128);   // q (bf16)
    gemm_relu<__nv_bfloat16><<<g128, 256>>>(nowkv, 256, W[10], Bv[10], kb, 128, 128); // k (bf16)
    gemm_relu<__nv_bfloat16><<<g128, 256>>>(valn, 128, W[11], Bv[11], vb, 128, 128);  // v (bf16)

    attn_kernel<<<dim3(NSEQ / 128, BSZ), 256, ATTN_SMEM>>>(qb, kb, vb, nowkv + 128, 256,
                                                           (float*)d_out);
}

// round 3
// speedup vs baseline: 5.4260x; 1.8951x over previous
#include <cuda_runtime.h>
#include <cuda_bf16.h>
#include <cstdint>

// Problem constants
#define PIX 16384        // B*H*W
#define NSEQ 4096        // H*W
#define BSZ 4
#define CH 128
#define THITA 1e-4f

// ---------------- scratch (device globals; no allocation allowed) -------------
__device__ float g_x4[PIX * 4];
__device__ float g_x2[PIX * 2];
__device__ float g_nowf[PIX * 128];
__device__ float g_nowval[PIX * 128];
__device__ __nv_bfloat16 g_neigh[PIX * 256];
__device__ __nv_bfloat16 g_keycat[PIX * 256];
__device__ __nv_bfloat16 g_valcat[PIX * 256];
__device__ __nv_bfloat16 g_keyn[PIX * 128];
__device__ __nv_bfloat16 g_valn[PIX * 128];
__device__ __nv_bfloat16 g_nowfb[PIX * 128];
__device__ __nv_bfloat16 g_nowkey[PIX * 128];
__device__ __nv_bfloat16 g_qb[PIX * 128];
__device__ __nv_bfloat16 g_kb[PIX * 128];
__device__ __nv_bfloat16 g_vb[PIX * 128];
// bf16 weights
__device__ __nv_bfloat16 g_wb1[256 * 128];   // [w_pro_key ; w_lat_key]
__device__ __nv_bfloat16 g_wb2[256 * 128];   // [w_pro_val ; w_lat_val]
__device__ __nv_bfloat16 g_wbt[128 * 256];   // w_tmp1
__device__ __nv_bfloat16 g_wbnk[128 * 128];  // w_now_key
__device__ __nv_bfloat16 g_wbq[128 * 128];
__device__ __nv_bfloat16 g_wbk[128 * 128];
__device__ __nv_bfloat16 g_wbv[128 * 128];
__device__ float g_bc1[256];
__device__ float g_bc2[256];

// ---------------- gather: split event planes into [pixel][chan] rows ----------
__global__ void __launch_bounds__(256) gather_kernel(const float* __restrict__ event,
                                                     float* __restrict__ x4,
                                                     float* __restrict__ x2) {
    int p = blockIdx.x * blockDim.x + threadIdx.x;
    if (p >= PIX) return;
    int b = p >> 12;
    int hw = p & 4095;
    const float* e = event + (size_t)b * 6 * NSEQ;
    x4[p * 4 + 0] = e[0 * NSEQ + hw];
    x4[p * 4 + 1] = e[1 * NSEQ + hw];
    x4[p * 4 + 2] = e[4 * NSEQ + hw];
    x4[p * 4 + 3] = e[5 * NSEQ + hw];
    x2[p * 2 + 0] = e[2 * NSEQ + hw];
    x2[p * 2 + 1] = e[3 * NSEQ + hw];
}

// ---------------- weight prep: fp32 -> bf16 (+ concats), one launch ----------
__global__ void __launch_bounds__(256) prep_w_kernel(
    const float* __restrict__ wpk, const float* __restrict__ wlk,
    const float* __restrict__ wpv, const float* __restrict__ wlv,
    const float* __restrict__ wt,  const float* __restrict__ wnk,
    const float* __restrict__ wq,  const float* __restrict__ wk,
    const float* __restrict__ wv,
    const float* __restrict__ bpk, const float* __restrict__ blk,
    const float* __restrict__ bpv, const float* __restrict__ blv) {
    int i = blockIdx.x * blockDim.x + threadIdx.x;   // 0..163839
    if (i < 32768) {
        g_wb1[i] = __float2bfloat16(i < 16384 ? wpk[i] : wlk[i - 16384]);
        g_wb2[i] = __float2bfloat16(i < 16384 ? wpv[i] : wlv[i - 16384]);
        g_wbt[i] = __float2bfloat16(wt[i]);
    } else if (i < 49152) {
        int j = i - 32768;
        if (j < 16384) g_wbnk[j] = __float2bfloat16(wnk[j]);
    } else if (i < 65536) {
        int j = i - 49152;
        g_wbq[j] = __float2bfloat16(wq[j]);
        g_wbk[j] = __float2bfloat16(wk[j]);
        g_wbv[j] = __float2bfloat16(wv[j]);
    }
    if (i < 256) {
        g_bc1[i] = i < 128 ? bpk[i] : blk[i - 128];
        g_bc2[i] = i < 128 ? bpv[i] : blv[i - 128];
    }
}

// ---------------- neighbor conv (K=4), elementwise, bf16 out -----------------
__global__ void __launch_bounds__(256) neighbor_kernel(
    const float4* __restrict__ x4, const float* __restrict__ w,
    const float* __restrict__ b, __nv_bfloat16* __restrict__ out) {
    int idx = blockIdx.x * blockDim.x + threadIdx.x;   // PIX*32
    int p = idx >> 5, cg = (idx & 31) * 8;
    float4 x = x4[p];
    uint32_t r[4];
#pragma unroll
    for (int j = 0; j < 4; j++) {
        int c0 = cg + 2 * j;
        float v0 = fmaf(w[c0 * 4 + 3], x.w, fmaf(w[c0 * 4 + 2], x.z,
                   fmaf(w[c0 * 4 + 1], x.y, fmaf(w[c0 * 4], x.x, b[c0]))));
        int c1 = c0 + 1;
        float v1 = fmaf(w[c1 * 4 + 3], x.w, fmaf(w[c1 * 4 + 2], x.z,
                   fmaf(w[c1 * 4 + 1], x.y, fmaf(w[c1 * 4], x.x, b[c1]))));
        v0 = fmaxf(v0, 0.f); v1 = fmaxf(v1, 0.f);
        asm("cvt.rn.bf16x2.f32 %0, %1, %2;" : "=r"(r[j]) : "f"(v1), "f"(v0));
    }
    *(uint4*)(out + (size_t)p * 256 + cg) = make_uint4(r[0], r[1], r[2], r[3]);
}

// ---------------- now_f conv (K=2), fp32 + bf16 outputs ----------------------
__global__ void __launch_bounds__(256) nowf_kernel(
    const float2* __restrict__ x2, const float* __restrict__ w,
    const float* __restrict__ b, float* __restrict__ outf,
    __nv_bfloat16* __restrict__ outb) {
    int idx = blockIdx.x * blockDim.x + threadIdx.x;   // PIX*16
    int p = idx >> 4, cg = (idx & 15) * 8;
    float2 x = x2[p];
    float v[8];
    uint32_t r[4];
#pragma unroll
    for (int j = 0; j < 8; j++) {
        int c = cg + j;
        v[j] = fmaxf(fmaf(w[c * 2 + 1], x.y, fmaf(w[c * 2], x.x, b[c])), 0.f);
    }
#pragma unroll
    for (int j = 0; j < 4; j++)
        asm("cvt.rn.bf16x2.f32 %0, %1, %2;" : "=r"(r[j]) : "f"(v[2 * j + 1]), "f"(v[2 * j]));
    float* of = outf + (size_t)p * 128 + cg;
    *(float4*)of = make_float4(v[0], v[1], v[2], v[3]);
    *(float4*)(of + 4) = make_float4(v[4], v[5], v[6], v[7]);
    *(uint4*)(outb + (size_t)p * 128 + cg) = make_uint4(r[0], r[1], r[2], r[3]);
}

// ---------------- fp32 relu-GEMM (precision-critical now_val only) -----------
__global__ void __launch_bounds__(256) gemm_relu_f32(
    const float* __restrict__ in, int in_ld,
    const float* __restrict__ w,
    const float* __restrict__ bias,
    float* __restrict__ out, int out_ld,
    int Cin) {
    __shared__ float As[16][65];
    __shared__ float Bs[16][65];
    const int tid = threadIdx.x;
    const int tx = tid & 15, ty = tid >> 4;
    const int m0 = blockIdx.x * 64;
    const int n0 = blockIdx.y * 64;
    float acc[4][4] = {};

    for (int k0 = 0; k0 < Cin; k0 += 16) {
        for (int i = tid; i < 64 * 16; i += 256) {
            int r = i >> 4, k = i & 15;
            As[k][r] = in[(size_t)(m0 + r) * in_ld + k0 + k];
            Bs[k][r] = w[(size_t)(n0 + r) * Cin + k0 + k];
        }
        __syncthreads();
#pragma unroll
        for (int k = 0; k < 16; k++) {
            float a[4], bb[4];
#pragma unroll
            for (int i = 0; i < 4; i++) a[i] = As[k][ty * 4 + i];
#pragma unroll
            for (int j = 0; j < 4; j++) bb[j] = Bs[k][tx * 4 + j];
#pragma unroll
            for (int i = 0; i < 4; i++)
#pragma unroll
                for (int j = 0; j < 4; j++)
                    acc[i][j] = fmaf(a[i], bb[j], acc[i][j]);
        }
        __syncthreads();
    }
#pragma unroll
    for (int j = 0; j < 4; j++) {
        float bj = bias[n0 + tx * 4 + j];
#pragma unroll
        for (int i = 0; i < 4; i++) {
            float r = acc[i][j] + bj;
            out[(size_t)(m0 + ty * 4 + i) * out_ld + n0 + tx * 4 + j] = r > 0.f ? r : 0.f;
        }
    }
}

// ---------------- mma / ldmatrix helpers --------------------------------------
__device__ __forceinline__ void mma16816(float* c, const uint32_t* a, const uint32_t* b) {
    asm volatile(
        "mma.sync.aligned.m16n8k16.row.col.f32.bf16.bf16.f32 "
        "{%0,%1,%2,%3}, {%4,%5,%6,%7}, {%8,%9}, {%0,%1,%2,%3};"
        : "+f"(c[0]), "+f"(c[1]), "+f"(c[2]), "+f"(c[3])
        : "r"(a[0]), "r"(a[1]), "r"(a[2]), "r"(a[3]), "r"(b[0]), "r"(b[1]));
}

__device__ __forceinline__ void ldsm4(uint32_t& r0, uint32_t& r1, uint32_t& r2, uint32_t& r3,
                                      const void* p) {
    uint32_t addr = (uint32_t)__cvta_generic_to_shared(p);
    asm volatile("ldmatrix.sync.aligned.m8n8.x4.shared.b16 {%0,%1,%2,%3}, [%4];"
                 : "=r"(r0), "=r"(r1), "=r"(r2), "=r"(r3) : "r"(addr));
}

__device__ __forceinline__ void ldsm4t(uint32_t& r0, uint32_t& r1, uint32_t& r2, uint32_t& r3,
                                       const void* p) {
    uint32_t addr = (uint32_t)__cvta_generic_to_shared(p);
    asm volatile("ldmatrix.sync.aligned.m8n8.x4.trans.shared.b16 {%0,%1,%2,%3}, [%4];"
                 : "=r"(r0), "=r"(r1), "=r"(r2), "=r"(r3) : "r"(addr));
}

__device__ __forceinline__ uint32_t packbf2(float lo, float hi) {
    uint32_t d;
    asm("cvt.rn.bf16x2.f32 %0, %1, %2;" : "=r"(d) : "f"(hi), "f"(lo));
    return d;
}

// ---------------- bf16 HMMA relu-GEMM: out = relu(in @ w^T + b), bf16 out ----
// BM=128, BN=128, BK=64. 256 threads = 8 warps (2 M x 4 N), warp tile 64x32.
__global__ void __launch_bounds__(256) gemm_bf16(
    const __nv_bfloat16* __restrict__ in, int in_ld,
    const __nv_bfloat16* __restrict__ w,      // [N][Cin]
    const float* __restrict__ bias,
    __nv_bfloat16* __restrict__ out, int out_ld,
    int Cin) {
    __shared__ uint4 As4[128 * 8];   // [128][64] bf16, 16B-chunk XOR swizzle
    __shared__ uint4 Bs4[128 * 8];
    __nv_bfloat16* As = (__nv_bfloat16*)As4;
    __nv_bfloat16* Bs = (__nv_bfloat16*)Bs4;

    const int tid = threadIdx.x, lane = tid & 31, wid = tid >> 5;
    const int m0 = blockIdx.x * 128, n0 = blockIdx.y * 128;
    const int wm = (wid & 1) * 64, wn = (wid >> 1) * 32;
    const int g = lane >> 2, tc = lane & 3;
    // A-operand ldmatrix lane map (a0..a3 = [rows0-7,k0-7],[rows8-15,k0-7],[rows0-7,k8-15],[rows8-15,k8-15])
    const int rA_loc = ((lane >> 3) & 1) * 8 + (lane & 7);
    const int cA_bit = (lane >> 4) & 1;
    // B-operand lane map (pairs {r0,r1}=first n8, {r2,r3}=second n8) — same as attn K
    const int rB_loc = ((lane >> 4) & 1) * 8 + (lane & 7);
    const int cB_bit = (lane >> 3) & 1;

    float acc[4][4][4];
#pragma unroll
    for (int i = 0; i < 4; i++)
#pragma unroll
        for (int j = 0; j < 4; j++)
#pragma unroll
            for (int l = 0; l < 4; l++) acc[i][j][l] = 0.f;

    for (int k0 = 0; k0 < Cin; k0 += 64) {
#pragma unroll
        for (int i = 0; i < 4; i++) {
            int li = tid + i * 256;
            int r = li >> 3, ch = li & 7;
            As4[r * 8 + (ch ^ (r & 7))] = *(const uint4*)(in + (size_t)(m0 + r) * in_ld + k0 + ch * 8);
            Bs4[r * 8 + (ch ^ (r & 7))] = *(const uint4*)(w + (size_t)(n0 + r) * Cin + k0 + ch * 8);
        }
        __syncthreads();
#pragma unroll
        for (int ks = 0; ks < 4; ks++) {
            uint32_t a[4][4], bf[2][4];
#pragma unroll
            for (int mi = 0; mi < 4; mi++) {
                int r = wm + mi * 16 + rA_loc;
                int ch = 2 * ks + cA_bit;
                ldsm4(a[mi][0], a[mi][1], a[mi][2], a[mi][3],
                      As + r * 64 + ((ch ^ (r & 7)) << 3));
            }
#pragma unroll
            for (int ni = 0; ni < 2; ni++) {
                int r = wn + ni * 16 + rB_loc;
                int ch = 2 * ks + cB_bit;
                ldsm4(bf[ni][0], bf[ni][1], bf[ni][2], bf[ni][3],
                      Bs + r * 64 + ((ch ^ (r & 7)) << 3));
            }
#pragma unroll
            for (int mi = 0; mi < 4; mi++)
#pragma unroll
                for (int ni = 0; ni < 2; ni++) {
                    uint32_t b0[2] = {bf[ni][0], bf[ni][1]};
                    mma16816(acc[mi][2 * ni], a[mi], b0);
                    uint32_t b1[2] = {bf[ni][2], bf[ni][3]};
                    mma16816(acc[mi][2 * ni + 1], a[mi], b1);
                }
        }
        __syncthreads();
    }
    // epilogue: bias + relu + bf16 store
#pragma unroll
    for (int mi = 0; mi < 4; mi++) {
        int r0 = m0 + wm + mi * 16 + g;
#pragma unroll
        for (int n8 = 0; n8 < 4; n8++) {
            int c = n0 + wn + n8 * 8 + 2 * tc;
            float2 bv = *(const float2*)(bias + c);
            float v0 = fmaxf(acc[mi][n8][0] + bv.x, 0.f);
            float v1 = fmaxf(acc[mi][n8][1] + bv.y, 0.f);
            float v2 = fmaxf(acc[mi][n8][2] + bv.x, 0.f);
            float v3 = fmaxf(acc[mi][n8][3] + bv.y, 0.f);
            *(uint32_t*)(out + (size_t)r0 * out_ld + c) = packbf2(v0, v1);
            *(uint32_t*)(out + (size_t)(r0 + 8) * out_ld + c) = packbf2(v2, v3);
        }
    }
}

// ---------------- fast exp (Schraudolph); args <= 0, clamp avoids wraparound --
__device__ __forceinline__ float fast_exp(float x) {
    x = fmaxf(x, -80.f);
    int i = (int)(fmaf(x, 12102203.0f, 1064866805.0f));
    return __int_as_float(i);
}

// ---------------- flash attention, bf16 HMMA, BM=128 BN=64 D=128 --------------
#define OPITCH 132
#define ATTN_SMEM (128 * OPITCH * 4)   // 67584 >= 2*64*128*2 (K+V bf16)

__global__ void __launch_bounds__(256, 1) attn_kernel(
    const __nv_bfloat16* __restrict__ gq,
    const __nv_bfloat16* __restrict__ gk,
    const __nv_bfloat16* __restrict__ gv,
    const float* __restrict__ gnv, int nv_ld,
    float* __restrict__ out) {
    extern __shared__ char smraw[];
    __nv_bfloat16* Ks = (__nv_bfloat16*)smraw;     // [64][128] swizzled
    __nv_bfloat16* Vs = Ks + 64 * 128;             // [64][128] swizzled
    float* OutS = (float*)smraw;                   // reused post-loop, [128][OPITCH]

    const int tid = threadIdx.x;
    const int lane = tid & 31, w = tid >> 5;
    const int g = lane >> 2, tc = lane & 3;
    const int b = blockIdx.y;
    const int q0 = blockIdx.x * 128;

    uint32_t qa[8][4];
    {
        const __nv_bfloat16* Qb = gq + ((size_t)(b * NSEQ) + q0 + w * 16) * CH;
#pragma unroll
        for (int kb = 0; kb < 8; kb++) {
            qa[kb][0] = *(const uint32_t*)(Qb + (size_t)g * CH + kb * 16 + 2 * tc);
            qa[kb][1] = *(const uint32_t*)(Qb + (size_t)(g + 8) * CH + kb * 16 + 2 * tc);
            qa[kb][2] = *(const uint32_t*)(Qb + (size_t)g * CH + kb * 16 + 8 + 2 * tc);
            qa[kb][3] = *(const uint32_t*)(Qb + (size_t)(g + 8) * CH + kb * 16 + 8 + 2 * tc);
        }
    }

    float O[16][4];
#pragma unroll
    for (int i = 0; i < 16; i++)
#pragma unroll
        for (int j = 0; j < 4; j++) O[i][j] = 0.f;
    float mrow0 = -1e30f, mrow1 = -1e30f, lrow0 = 0.f, lrow1 = 0.f;

    const int rK_loc = ((lane >> 4) & 1) * 8 + (lane & 7);
    const int cK_bit = (lane >> 3) & 1;
    const int rV_loc = ((lane >> 3) & 1) * 8 + (lane & 7);
    const int cV_bit = lane >> 4;

    const __nv_bfloat16* Kgb = gk + (size_t)b * NSEQ * CH;
    const __nv_bfloat16* Vgb = gv + (size_t)b * NSEQ * CH;

    for (int jt = 0; jt < NSEQ / 64; jt++) {
        __syncthreads();
        {
            const uint4* Kg = (const uint4*)(Kgb + (size_t)jt * 64 * CH);
            const uint4* Vg = (const uint4*)(Vgb + (size_t)jt * 64 * CH);
#pragma unroll
            for (int i = tid; i < 1024; i += 256) {
                int r = i >> 4, ch = i & 15;
                int sch = ch ^ (r & 7);
                ((uint4*)Ks)[r * 16 + sch] = Kg[i];
                ((uint4*)Vs)[r * 16 + sch] = Vg[i];
            }
        }
        __syncthreads();

        float S[8][4];
#pragma unroll
        for (int i = 0; i < 8; i++)
#pragma unroll
            for (int j = 0; j < 4; j++) S[i][j] = 0.f;
#pragma unroll
        for (int kb = 0; kb < 8; kb++) {
#pragma unroll
            for (int p = 0; p < 4; p++) {
                int r = p * 16 + rK_loc;
                int ch = 2 * kb + cK_bit;
                uint32_t b0, b1, b2, b3;
                ldsm4(b0, b1, b2, b3, Ks + r * 128 + ((ch ^ (r & 7)) << 3));
                uint32_t bb[2] = {b0, b1};
                mma16816(S[2 * p], qa[kb], bb);
                uint32_t bb2[2] = {b2, b3};
                mma16816(S[2 * p + 1], qa[kb], bb2);
            }
        }

        float m0 = -1e30f, m1 = -1e30f;
#pragma unroll
        for (int nb = 0; nb < 8; nb++) {
            m0 = fmaxf(m0, fmaxf(S[nb][0], S[nb][1]));
            m1 = fmaxf(m1, fmaxf(S[nb][2], S[nb][3]));
        }
        m0 = fmaxf(m0, __shfl_xor_sync(0xffffffffu, m0, 1));
        m0 = fmaxf(m0, __shfl_xor_sync(0xffffffffu, m0, 2));
        m1 = fmaxf(m1, __shfl_xor_sync(0xffffffffu, m1, 1));
        m1 = fmaxf(m1, __shfl_xor_sync(0xffffffffu, m1, 2));
        float mn0 = fmaxf(mrow0, m0), mn1 = fmaxf(mrow1, m1);
        float scl0 = fast_exp(mrow0 - mn0), scl1 = fast_exp(mrow1 - mn1);
        mrow0 = mn0; mrow1 = mn1;
        float rs0 = 0.f, rs1 = 0.f;
#pragma unroll
        for (int nb = 0; nb < 8; nb++) {
            S[nb][0] = fast_exp(S[nb][0] - mn0);
            S[nb][1] = fast_exp(S[nb][1] - mn0);
            S[nb][2] = fast_exp(S[nb][2] - mn1);
            S[nb][3] = fast_exp(S[nb][3] - mn1);
            rs0 += S[nb][0] + S[nb][1];
            rs1 += S[nb][2] + S[nb][3];
        }
        rs0 += __shfl_xor_sync(0xffffffffu, rs0, 1);
        rs0 += __shfl_xor_sync(0xffffffffu, rs0, 2);
        rs1 += __shfl_xor_sync(0xffffffffu, rs1, 1);
        rs1 += __shfl_xor_sync(0xffffffffu, rs1, 2);
        lrow0 = lrow0 * scl0 + rs0;
        lrow1 = lrow1 * scl1 + rs1;
#pragma unroll
        for (int nb = 0; nb < 16; nb++) {
            O[nb][0] *= scl0; O[nb][1] *= scl0;
            O[nb][2] *= scl1; O[nb][3] *= scl1;
        }

        uint32_t pa[4][4];
#pragma unroll
        for (int jb = 0; jb < 4; jb++) {
            pa[jb][0] = packbf2(S[2 * jb][0], S[2 * jb][1]);
            pa[jb][1] = packbf2(S[2 * jb][2], S[2 * jb][3]);
            pa[jb][2] = packbf2(S[2 * jb + 1][0], S[2 * jb + 1][1]);
            pa[jb][3] = packbf2(S[2 * jb + 1][2], S[2 * jb + 1][3]);
        }

#pragma unroll
        for (int jb = 0; jb < 4; jb++) {
            int r = jb * 16 + rV_loc;
#pragma unroll
            for (int cp = 0; cp < 8; cp++) {
                int ch = 2 * cp + cV_bit;
                uint32_t b0, b1, b2, b3;
                ldsm4t(b0, b1, b2, b3, Vs + r * 128 + ((ch ^ (r & 7)) << 3));
                uint32_t bb[2] = {b0, b1};
                mma16816(O[2 * cp], pa[jb], bb);
                uint32_t bb2[2] = {b2, b3};
                mma16816(O[2 * cp + 1], pa[jb], bb2);
            }
        }
    }

    __syncthreads();
    {
        float inv0 = 1.f / lrow0, inv1 = 1.f / lrow1;
        int row0 = w * 16 + g, row1 = row0 + 8;
        const float* nvp0 = gnv + ((size_t)(b * NSEQ) + q0 + row0) * nv_ld;
        const float* nvp1 = gnv + ((size_t)(b * NSEQ) + q0 + row1) * nv_ld;
#pragma unroll
        for (int nb = 0; nb < 16; nb++) {
            int c = nb * 8 + 2 * tc;
            float2 nv0 = *(const float2*)(nvp0 + c);
            float2 nv1 = *(const float2*)(nvp1 + c);
            OutS[c * OPITCH + row0] = fmaf(THITA, O[nb][0] * inv0, nv0.x);
            OutS[(c + 1) * OPITCH + row0] = fmaf(THITA, O[nb][1] * inv0, nv0.y);
            OutS[c * OPITCH + row1] = fmaf(THITA, O[nb][2] * inv1, nv1.x);
            OutS[(c + 1) * OPITCH + row1] = fmaf(THITA, O[nb][3] * inv1, nv1.y);
        }
    }
    __syncthreads();
    {
        float* ob = out + (size_t)b * CH * NSEQ + q0;
        for (int i = tid; i < 128 * 128 / 4; i += 256) {
            int idx = i * 4;
            int c = idx >> 7, nl = idx & 127;
            float4 v = *(const float4*)(OutS + c * OPITCH + nl);
            *(float4*)(ob + (size_t)c * NSEQ + nl) = v;
        }
    }
}

// ---------------- host launch --------------------------------------------------
extern "C" void kernel_launch(void* const* d_in, const int* in_sizes, int n_in,
                              void* d_out, int out_size) {
    const float* event = (const float*)d_in[0];
    const float* W[12];
    const float* Bv[12];
    for (int i = 0; i < 12; i++) {
        W[i] = (const float*)d_in[1 + 2 * i];
        Bv[i] = (const float*)d_in[2 + 2 * i];
    }
    // 0 neighbor, 1 pro_key, 2 pro_val, 3 lat_key, 4 lat_val, 5 tmp1,
    // 6 now1, 7 now_key, 8 now_val, 9 q, 10 k, 11 v

    float *x4, *x2, *nowf, *nowval, *bc1, *bc2;
    __nv_bfloat16 *neigh, *keycat, *valcat, *keyn, *valn, *nowfb, *nowkey, *qb, *kb, *vb;
    __nv_bfloat16 *wb1, *wb2, *wbt, *wbnk, *wbq, *wbk, *wbv;
    cudaGetSymbolAddress((void**)&x4, g_x4);
    cudaGetSymbolAddress((void**)&x2, g_x2);
    cudaGetSymbolAddress((void**)&nowf, g_nowf);
    cudaGetSymbolAddress((void**)&nowval, g_nowval);
    cudaGetSymbolAddress((void**)&neigh, g_neigh);
    cudaGetSymbolAddress((void**)&keycat, g_keycat);
    cudaGetSymbolAddress((void**)&valcat, g_valcat);
    cudaGetSymbolAddress((void**)&keyn, g_keyn);
    cudaGetSymbolAddress((void**)&valn, g_valn);
    cudaGetSymbolAddress((void**)&nowfb, g_nowfb);
    cudaGetSymbolAddress((void**)&nowkey, g_nowkey);
    cudaGetSymbolAddress((void**)&qb, g_qb);
    cudaGetSymbolAddress((void**)&kb, g_kb);
    cudaGetSymbolAddress((void**)&vb, g_vb);
    cudaGetSymbolAddress((void**)&wb1, g_wb1);
    cudaGetSymbolAddress((void**)&wb2, g_wb2);
    cudaGetSymbolAddress((void**)&wbt, g_wbt);
    cudaGetSymbolAddress((void**)&wbnk, g_wbnk);
    cudaGetSymbolAddress((void**)&wbq, g_wbq);
    cudaGetSymbolAddress((void**)&wbk, g_wbk);
    cudaGetSymbolAddress((void**)&wbv, g_wbv);
    cudaGetSymbolAddress((void**)&bc1, g_bc1);
    cudaGetSymbolAddress((void**)&bc2, g_bc2);

    cudaFuncSetAttribute(attn_kernel, cudaFuncAttributeMaxDynamicSharedMemorySize, ATTN_SMEM);

    gather_kernel<<<PIX / 256, 256>>>(event, x4, x2);
    prep_w_kernel<<<640, 256>>>(W[1], W[3], W[2], W[4], W[5], W[7], W[9], W[10], W[11],
                                Bv[1], Bv[3], Bv[2], Bv[4]);

    neighbor_kernel<<<PIX * 32 / 256, 256>>>((const float4*)x4, W[0], Bv[0], neigh);
    nowf_kernel<<<PIX * 16 / 256, 256>>>((const float2*)x2, W[6], Bv[6], nowf, nowfb);

    dim3 gA(PIX / 128, 2);   // N = 256
    dim3 gB(PIX / 128, 1);   // N = 128
    gemm_bf16<<<gA, 256>>>(neigh, 256, wb1, bc1, keycat, 256, 128);        // [pro_key|lat_key]
    gemm_bf16<<<gA, 256>>>(neigh + 128, 256, wb2, bc2, valcat, 256, 128);  // [pro_val|lat_val]
    gemm_bf16<<<gB, 256>>>(keycat, 256, wbt, Bv[5], keyn, 128, 256);       // key_n
    gemm_bf16<<<gB, 256>>>(valcat, 256, wbt, Bv[5], valn, 128, 256);       // val_n
    gemm_bf16<<<gB, 256>>>(nowfb, 128, wbnk, Bv[7], nowkey, 128, 128);     // now_key
    gemm_relu_f32<<<dim3(PIX / 64, 2), 256>>>(nowf, 128, W[8], Bv[8], nowval, 128, 128); // now_val (fp32)
    gemm_bf16<<<gB, 256>>>(keyn, 128, wbq, Bv[9], qb, 128, 128);           // q
    gemm_bf16<<<gB, 256>>>(nowkey, 128, wbk, Bv[10], kb, 128, 128);        // k
    gemm_bf16<<<gB, 256>>>(valn, 128, wbv, Bv[11], vb, 128, 128);          // v

    attn_kernel<<<dim3(NSEQ / 128, BSZ), 256, ATTN_SMEM>>>(qb, kb, vb, nowval, 128,
                                                           (float*)d_out);
}

// round 5
// speedup vs baseline: 6.4835x; 1.1949x over previous
#include <cuda_runtime.h>
#include <cuda_bf16.h>
#include <cstdint>

// Problem constants
#define PIX 16384        // B*H*W
#define NSEQ 4096        // H*W
#define BSZ 4
#define CH 128
#define THITA 1e-4f

// ---------------- scratch (device globals; no allocation allowed) -------------
__device__ float g_nowval[PIX * 128];
__device__ __nv_bfloat16 g_neigh[PIX * 256];
__device__ __nv_bfloat16 g_keycat[PIX * 256];
__device__ __nv_bfloat16 g_valcat[PIX * 256];
__device__ __nv_bfloat16 g_keyn[PIX * 128];
__device__ __nv_bfloat16 g_valn[PIX * 128];
__device__ __nv_bfloat16 g_nowfb[PIX * 128];
__device__ __nv_bfloat16 g_nowkey[PIX * 128];
__device__ __nv_bfloat16 g_qb[PIX * 128];
__device__ __nv_bfloat16 g_kb[PIX * 128];
__device__ __nv_bfloat16 g_vb[PIX * 128];
// bf16 weights
__device__ __nv_bfloat16 g_wb1[256 * 128];   // [w_pro_key ; w_lat_key]
__device__ __nv_bfloat16 g_wb2[256 * 128];   // [w_pro_val ; w_lat_val]
__device__ __nv_bfloat16 g_wbt[128 * 256];   // w_tmp1
__device__ __nv_bfloat16 g_wbnk[128 * 128];  // w_now_key
__device__ __nv_bfloat16 g_wbq[128 * 128];
__device__ __nv_bfloat16 g_wbk[128 * 128];
__device__ __nv_bfloat16 g_wbv[128 * 128];
__device__ __nv_bfloat16 g_w8hi[128 * 128];  // w_now_val split hi
__device__ __nv_bfloat16 g_w8lo[128 * 128];  // w_now_val split lo
__device__ float g_bc1[256];
__device__ float g_bc2[256];

// ---------------- weight prep: fp32 -> bf16 (+ concats + now_val split) ------
__global__ void __launch_bounds__(256) prep_w_kernel(
    const float* __restrict__ wpk, const float* __restrict__ wlk,
    const float* __restrict__ wpv, const float* __restrict__ wlv,
    const float* __restrict__ wt,  const float* __restrict__ wnk,
    const float* __restrict__ wq,  const float* __restrict__ wk,
    const float* __restrict__ wv,  const float* __restrict__ wnv,
    const float* __restrict__ bpk, const float* __restrict__ blk,
    const float* __restrict__ bpv, const float* __restrict__ blv) {
    int i = blockIdx.x * blockDim.x + threadIdx.x;   // 0..163839
    if (i < 32768) {
        g_wb1[i] = __float2bfloat16(i < 16384 ? wpk[i] : wlk[i - 16384]);
        g_wb2[i] = __float2bfloat16(i < 16384 ? wpv[i] : wlv[i - 16384]);
        g_wbt[i] = __float2bfloat16(wt[i]);
    } else if (i < 49152) {
        int j = i - 32768;
        if (j < 16384) {
            g_wbnk[j] = __float2bfloat16(wnk[j]);
            float v = wnv[j];
            __nv_bfloat16 h = __float2bfloat16(v);
            g_w8hi[j] = h;
            g_w8lo[j] = __float2bfloat16(v - __bfloat162float(h));
        }
    } else if (i < 65536) {
        int j = i - 49152;
        g_wbq[j] = __float2bfloat16(wq[j]);
        g_wbk[j] = __float2bfloat16(wk[j]);
        g_wbv[j] = __float2bfloat16(wv[j]);
    }
    if (i < 256) {
        g_bc1[i] = i < 128 ? bpk[i] : blk[i - 128];
        g_bc2[i] = i < 128 ? bpv[i] : blv[i - 128];
    }
}

// ---------------- neighbor conv (K=4) straight from event, bf16 out ----------
__global__ void __launch_bounds__(256) neighbor_kernel(
    const float* __restrict__ event, const float* __restrict__ w,
    const float* __restrict__ b, __nv_bfloat16* __restrict__ out) {
    int idx = blockIdx.x * blockDim.x + threadIdx.x;   // PIX*32
    int p = idx >> 5, cg = (idx & 31) * 8;
    int bb = p >> 12, hw = p & 4095;
    const float* e = event + (size_t)bb * 6 * NSEQ + hw;
    float x0 = e[0], x1 = e[NSEQ], x2 = e[4 * NSEQ], x3 = e[5 * NSEQ];
    uint32_t r[4];
#pragma unroll
    for (int j = 0; j < 4; j++) {
        int c0 = cg + 2 * j;
        float v0 = fmaf(w[c0 * 4 + 3], x3, fmaf(w[c0 * 4 + 2], x2,
                   fmaf(w[c0 * 4 + 1], x1, fmaf(w[c0 * 4], x0, b[c0]))));
        int c1 = c0 + 1;
        float v1 = fmaf(w[c1 * 4 + 3], x3, fmaf(w[c1 * 4 + 2], x2,
                   fmaf(w[c1 * 4 + 1], x1, fmaf(w[c1 * 4], x0, b[c1]))));
        v0 = fmaxf(v0, 0.f); v1 = fmaxf(v1, 0.f);
        asm("cvt.rn.bf16x2.f32 %0, %1, %2;" : "=r"(r[j]) : "f"(v1), "f"(v0));
    }
    *(uint4*)(out + (size_t)p * 256 + cg) = make_uint4(r[0], r[1], r[2], r[3]);
}

// ---------------- now_f conv (K=2) straight from event, bf16 out -------------
__global__ void __launch_bounds__(256) nowf_kernel(
    const float* __restrict__ event, const float* __restrict__ w,
    const float* __restrict__ b, __nv_bfloat16* __restrict__ outb) {
    int idx = blockIdx.x * blockDim.x + threadIdx.x;   // PIX*16
    int p = idx >> 4, cg = (idx & 15) * 8;
    int bb = p >> 12, hw = p & 4095;
    const float* e = event + (size_t)bb * 6 * NSEQ + hw;
    float x = e[2 * NSEQ], y = e[3 * NSEQ];
    uint32_t r[4];
#pragma unroll
    for (int j = 0; j < 4; j++) {
        int c0 = cg + 2 * j, c1 = c0 + 1;
        float v0 = fmaxf(fmaf(w[c0 * 2 + 1], y, fmaf(w[c0 * 2], x, b[c0])), 0.f);
        float v1 = fmaxf(fmaf(w[c1 * 2 + 1], y, fmaf(w[c1 * 2], x, b[c1])), 0.f);
        asm("cvt.rn.bf16x2.f32 %0, %1, %2;" : "=r"(r[j]) : "f"(v1), "f"(v0));
    }
    *(uint4*)(outb + (size_t)p * 128 + cg) = make_uint4(r[0], r[1], r[2], r[3]);
}

// ---------------- mma / ldmatrix helpers --------------------------------------
__device__ __forceinline__ void mma16816(float* c, const uint32_t* a, const uint32_t* b) {
    asm volatile(
        "mma.sync.aligned.m16n8k16.row.col.f32.bf16.bf16.f32 "
        "{%0,%1,%2,%3}, {%4,%5,%6,%7}, {%8,%9}, {%0,%1,%2,%3};"
        : "+f"(c[0]), "+f"(c[1]), "+f"(c[2]), "+f"(c[3])
        : "r"(a[0]), "r"(a[1]), "r"(a[2]), "r"(a[3]), "r"(b[0]), "r"(b[1]));
}

__device__ __forceinline__ void ldsm4(uint32_t& r0, uint32_t& r1, uint32_t& r2, uint32_t& r3,
                                      const void* p) {
    uint32_t addr = (uint32_t)__cvta_generic_to_shared(p);
    asm volatile("ldmatrix.sync.aligned.m8n8.x4.shared.b16 {%0,%1,%2,%3}, [%4];"
                 : "=r"(r0), "=r"(r1), "=r"(r2), "=r"(r3) : "r"(addr));
}

__device__ __forceinline__ void ldsm4t(uint32_t& r0, uint32_t& r1, uint32_t& r2, uint32_t& r3,
                                       const void* p) {
    uint32_t addr = (uint32_t)__cvta_generic_to_shared(p);
    asm volatile("ldmatrix.sync.aligned.m8n8.x4.trans.shared.b16 {%0,%1,%2,%3}, [%4];"
                 : "=r"(r0), "=r"(r1), "=r"(r2), "=r"(r3) : "r"(addr));
}

__device__ __forceinline__ uint32_t packbf2(float lo, float hi) {
    uint32_t d;
    asm("cvt.rn.bf16x2.f32 %0, %1, %2;" : "=r"(d) : "f"(hi), "f"(lo));
    return d;
}

__device__ __forceinline__ void cpasync16(void* dst, const void* src) {
    uint32_t d = (uint32_t)__cvta_generic_to_shared(dst);
    asm volatile("cp.async.cg.shared.global [%0], [%1], 16;" :: "r"(d), "l"(src));
}
#define CP_COMMIT() asm volatile("cp.async.commit_group;")
#define CP_WAIT1()  asm volatile("cp.async.wait_group 1;")

// ---------------- bf16 HMMA relu-GEMM: out = relu(in @ w^T + b), bf16 out ----
// BM=128, BN=128, BK=64. 256 threads = 8 warps (2 M x 4 N), warp tile 64x32.
__global__ void __launch_bounds__(256) gemm_bf16(
    const __nv_bfloat16* __restrict__ in, int in_ld,
    const __nv_bfloat16* __restrict__ w,      // [N][Cin]
    const float* __restrict__ bias,
    __nv_bfloat16* __restrict__ out, int out_ld,
    int Cin) {
    __shared__ uint4 As4[128 * 8];   // [128][64] bf16, 16B-chunk XOR swizzle
    __shared__ uint4 Bs4[128 * 8];
    __nv_bfloat16* As = (__nv_bfloat16*)As4;
    __nv_bfloat16* Bs = (__nv_bfloat16*)Bs4;

    const int tid = threadIdx.x, lane = tid & 31, wid = tid >> 5;
    const int m0 = blockIdx.x * 128, n0 = blockIdx.y * 128;
    const int wm = (wid & 1) * 64, wn = (wid >> 1) * 32;
    const int g = lane >> 2, tc = lane & 3;
    const int rA_loc = ((lane >> 3) & 1) * 8 + (lane & 7);
    const int cA_bit = (lane >> 4) & 1;
    const int rB_loc = ((lane >> 4) & 1) * 8 + (lane & 7);
    const int cB_bit = (lane >> 3) & 1;

    float acc[4][4][4];
#pragma unroll
    for (int i = 0; i < 4; i++)
#pragma unroll
        for (int j = 0; j < 4; j++)
#pragma unroll
            for (int l = 0; l < 4; l++) acc[i][j][l] = 0.f;

    for (int k0 = 0; k0 < Cin; k0 += 64) {
#pragma unroll
        for (int i = 0; i < 4; i++) {
            int li = tid + i * 256;
            int r = li >> 3, ch = li & 7;
            As4[r * 8 + (ch ^ (r & 7))] = *(const uint4*)(in + (size_t)(m0 + r) * in_ld + k0 + ch * 8);
            Bs4[r * 8 + (ch ^ (r & 7))] = *(const uint4*)(w + (size_t)(n0 + r) * Cin + k0 + ch * 8);
        }
        __syncthreads();
#pragma unroll
        for (int ks = 0; ks < 4; ks++) {
            uint32_t a[4][4], bf[2][4];
#pragma unroll
            for (int mi = 0; mi < 4; mi++) {
                int r = wm + mi * 16 + rA_loc;
                int ch = 2 * ks + cA_bit;
                ldsm4(a[mi][0], a[mi][1], a[mi][2], a[mi][3],
                      As + r * 64 + ((ch ^ (r & 7)) << 3));
            }
#pragma unroll
            for (int ni = 0; ni < 2; ni++) {
                int r = wn + ni * 16 + rB_loc;
                int ch = 2 * ks + cB_bit;
                ldsm4(bf[ni][0], bf[ni][1], bf[ni][2], bf[ni][3],
                      Bs + r * 64 + ((ch ^ (r & 7)) << 3));
            }
#pragma unroll
            for (int mi = 0; mi < 4; mi++)
#pragma unroll
                for (int ni = 0; ni < 2; ni++) {
                    uint32_t b0[2] = {bf[ni][0], bf[ni][1]};
                    mma16816(acc[mi][2 * ni], a[mi], b0);
                    uint32_t b1[2] = {bf[ni][2], bf[ni][3]};
                    mma16816(acc[mi][2 * ni + 1], a[mi], b1);
                }
        }
        __syncthreads();
    }
#pragma unroll
    for (int mi = 0; mi < 4; mi++) {
        int r0 = m0 + wm + mi * 16 + g;
#pragma unroll
        for (int n8 = 0; n8 < 4; n8++) {
            int c = n0 + wn + n8 * 8 + 2 * tc;
            float2 bv = *(const float2*)(bias + c);
            float v0 = fmaxf(acc[mi][n8][0] + bv.x, 0.f);
            float v1 = fmaxf(acc[mi][n8][1] + bv.y, 0.f);
            float v2 = fmaxf(acc[mi][n8][2] + bv.x, 0.f);
            float v3 = fmaxf(acc[mi][n8][3] + bv.y, 0.f);
            *(uint32_t*)(out + (size_t)r0 * out_ld + c) = packbf2(v0, v1);
            *(uint32_t*)(out + (size_t)(r0 + 8) * out_ld + c) = packbf2(v2, v3);
        }
    }
}

// ---------------- now_val: fused nowf (K=2, fp32 on the fly) + split-bf16 GEMM
// out = relu( relu(W6 @ x2 + b6) @ W8^T + b8 ) in ~fp32 precision via
// A*B ~= Ah*Bh + Ah*Bl + Al*Bh. BM=128, BN=128 (full), fp32 out.
#define NV_SMEM (65536 + 1024 + 1024 + 512)

__global__ void __launch_bounds__(256) gemm_nowval(
    const float* __restrict__ event,
    const float* __restrict__ w6, const float* __restrict__ b6,
    const __nv_bfloat16* __restrict__ w8hi, const __nv_bfloat16* __restrict__ w8lo,
    const float* __restrict__ b8,
    float* __restrict__ out) {
    extern __shared__ char sm[];
    __nv_bfloat16* Ah = (__nv_bfloat16*)sm;            // [128][64] swizzled
    __nv_bfloat16* Al = Ah + 128 * 64;
    __nv_bfloat16* Bh = Al + 128 * 64;
    __nv_bfloat16* Bl = Bh + 128 * 64;
    float* x2s = (float*)(sm + 65536);                 // [128][2]
    float* w6s = x2s + 256;                            // [128][2]
    float* b6s = w6s + 256;                            // [128]

    const int tid = threadIdx.x, lane = tid & 31, wid = tid >> 5;
    const int m0 = blockIdx.x * 128;
    const int wm = (wid & 1) * 64, wn = (wid >> 1) * 32;
    const int g = lane >> 2, tc = lane & 3;
    const int rA_loc = ((lane >> 3) & 1) * 8 + (lane & 7);
    const int cA_bit = (lane >> 4) & 1;
    const int rB_loc = ((lane >> 4) & 1) * 8 + (lane & 7);
    const int cB_bit = (lane >> 3) & 1;

    {
        int bb = m0 >> 12;
        const float* e = event + (size_t)bb * 6 * NSEQ + (m0 & 4095);
        if (tid < 128) {
            x2s[2 * tid] = e[2 * NSEQ + tid];
            x2s[2 * tid + 1] = e[3 * NSEQ + tid];
            b6s[tid] = b6[tid];
        } else {
            int j = tid - 128;
            ((float2*)w6s)[j] = ((const float2*)w6)[j];
        }
    }
    __syncthreads();

    float acc[4][4][4];
#pragma unroll
    for (int i = 0; i < 4; i++)
#pragma unroll
        for (int j = 0; j < 4; j++)
#pragma unroll
            for (int l = 0; l < 4; l++) acc[i][j][l] = 0.f;

    for (int k0 = 0; k0 < 128; k0 += 64) {
#pragma unroll
        for (int i = 0; i < 4; i++) {
            int li = tid + i * 256;
            int r = li >> 3, cch = li & 7;
            // A chunk: compute nowf fp32, split hi/lo
            float x0 = x2s[2 * r], x1 = x2s[2 * r + 1];
            uint4 hq, lq;
            __nv_bfloat16* hp = (__nv_bfloat16*)&hq;
            __nv_bfloat16* lp = (__nv_bfloat16*)&lq;
#pragma unroll
            for (int j = 0; j < 8; j++) {
                int k = k0 + cch * 8 + j;
                float v = fmaxf(fmaf(w6s[2 * k + 1], x1, fmaf(w6s[2 * k], x0, b6s[k])), 0.f);
                __nv_bfloat16 h = __float2bfloat16(v);
                hp[j] = h;
                lp[j] = __float2bfloat16(v - __bfloat162float(h));
            }
            int sidx = r * 8 + (cch ^ (r & 7));
            ((uint4*)Ah)[sidx] = hq;
            ((uint4*)Al)[sidx] = lq;
            // B chunk
            ((uint4*)Bh)[sidx] = *(const uint4*)(w8hi + (size_t)r * 128 + k0 + cch * 8);
            ((uint4*)Bl)[sidx] = *(const uint4*)(w8lo + (size_t)r * 128 + k0 + cch * 8);
        }
        __syncthreads();
#pragma unroll
        for (int ks = 0; ks < 4; ks++) {
            uint32_t ah[4][4], al[4][4], bh[2][4], bl[2][4];
#pragma unroll
            for (int mi = 0; mi < 4; mi++) {
                int r = wm + mi * 16 + rA_loc;
                int ch = 2 * ks + cA_bit;
                int off = r * 64 + ((ch ^ (r & 7)) << 3);
                ldsm4(ah[mi][0], ah[mi][1], ah[mi][2], ah[mi][3], Ah + off);
                ldsm4(al[mi][0], al[mi][1], al[mi][2], al[mi][3], Al + off);
            }
#pragma unroll
            for (int ni = 0; ni < 2; ni++) {
                int r = wn + ni * 16 + rB_loc;
                int ch = 2 * ks + cB_bit;
                int off = r * 64 + ((ch ^ (r & 7)) << 3);
                ldsm4(bh[ni][0], bh[ni][1], bh[ni][2], bh[ni][3], Bh + off);
                ldsm4(bl[ni][0], bl[ni][1], bl[ni][2], bl[ni][3], Bl + off);
            }
#pragma unroll
            for (int mi = 0; mi < 4; mi++)
#pragma unroll
                for (int ni = 0; ni < 2; ni++) {
                    uint32_t h0[2] = {bh[ni][0], bh[ni][1]};
                    uint32_t h1[2] = {bh[ni][2], bh[ni][3]};
                    uint32_t l0[2] = {bl[ni][0], bl[ni][1]};
                    uint32_t l1[2] = {bl[ni][2], bl[ni][3]};
                    mma16816(acc[mi][2 * ni], ah[mi], h0);
                    mma16816(acc[mi][2 * ni + 1], ah[mi], h1);
                    mma16816(acc[mi][2 * ni], ah[mi], l0);
                    mma16816(acc[mi][2 * ni + 1], ah[mi], l1);
                    mma16816(acc[mi][2 * ni], al[mi], h0);
                    mma16816(acc[mi][2 * ni + 1], al[mi], h1);
                }
        }
        __syncthreads();
    }
#pragma unroll
    for (int mi = 0; mi < 4; mi++) {
        int r0 = m0 + wm + mi * 16 + g;
#pragma unroll
        for (int n8 = 0; n8 < 4; n8++) {
            int c = wn + n8 * 8 + 2 * tc;
            float2 bv = *(const float2*)(b8 + c);
            float2 v01, v23;
            v01.x = fmaxf(acc[mi][n8][0] + bv.x, 0.f);
            v01.y = fmaxf(acc[mi][n8][1] + bv.y, 0.f);
            v23.x = fmaxf(acc[mi][n8][2] + bv.x, 0.f);
            v23.y = fmaxf(acc[mi][n8][3] + bv.y, 0.f);
            *(float2*)(out + (size_t)r0 * 128 + c) = v01;
            *(float2*)(out + (size_t)(r0 + 8) * 128 + c) = v23;
        }
    }
}

// ---------------- fast exp (Schraudolph); args <= 0, clamp avoids wraparound --
__device__ __forceinline__ float fast_exp(float x) {
    x = fmaxf(x, -80.f);
    int i = (int)(fmaf(x, 12102203.0f, 1064866805.0f));
    return __int_as_float(i);
}

// ---------------- flash attention, bf16 HMMA, BM=128 BN=64, 2-stage cp.async --
#define OPITCH 132
#define ATTN_SMEM (128 * OPITCH * 4)   // 67584 >= 2 stages * 32KB KV

__global__ void __launch_bounds__(256, 1) attn_kernel(
    const __nv_bfloat16* __restrict__ gq,
    const __nv_bfloat16* __restrict__ gk,
    const __nv_bfloat16* __restrict__ gv,
    const float* __restrict__ gnv, int nv_ld,
    float* __restrict__ out) {
    extern __shared__ char smraw[];
    float* OutS = (float*)smraw;                   // reused post-loop, [128][OPITCH]

    const int tid = threadIdx.x;
    const int lane = tid & 31, w = tid >> 5;
    const int g = lane >> 2, tc = lane & 3;
    const int b = blockIdx.y;
    const int q0 = blockIdx.x * 128;

    uint32_t qa[8][4];
    {
        const __nv_bfloat16* Qb = gq + ((size_t)(b * NSEQ) + q0 + w * 16) * CH;
#pragma unroll
        for (int kb = 0; kb < 8; kb++) {
            qa[kb][0] = *(const uint32_t*)(Qb + (size_t)g * CH + kb * 16 + 2 * tc);
            qa[kb][1] = *(const uint32_t*)(Qb + (size_t)(g + 8) * CH + kb * 16 + 2 * tc);
            qa[kb][2] = *(const uint32_t*)(Qb + (size_t)g * CH + kb * 16 + 8 + 2 * tc);
            qa[kb][3] = *(const uint32_t*)(Qb + (size_t)(g + 8) * CH + kb * 16 + 8 + 2 * tc);
        }
    }

    float O[16][4];
#pragma unroll
    for (int i = 0; i < 16; i++)
#pragma unroll
        for (int j = 0; j < 4; j++) O[i][j] = 0.f;
    float mrow0 = -1e30f, mrow1 = -1e30f, lrow0 = 0.f, lrow1 = 0.f;

    const int rK_loc = ((lane >> 4) & 1) * 8 + (lane & 7);
    const int cK_bit = (lane >> 3) & 1;
    const int rV_loc = ((lane >> 3) & 1) * 8 + (lane & 7);
    const int cV_bit = lane >> 4;

    const __nv_bfloat16* Kgb = gk + (size_t)b * NSEQ * CH;
    const __nv_bfloat16* Vgb = gv + (size_t)b * NSEQ * CH;

    // stage tile jt into buffer s via cp.async
    auto stage = [&](int jt, int s) {
        const uint4* Kg = (const uint4*)(Kgb + (size_t)jt * 64 * CH);
        const uint4* Vg = (const uint4*)(Vgb + (size_t)jt * 64 * CH);
        uint4* Kd = (uint4*)(smraw + s * 32768);
        uint4* Vd = Kd + 1024;
#pragma unroll
        for (int i = tid; i < 1024; i += 256) {
            int r = i >> 4, ch = i & 15, sch = ch ^ (r & 7);
            cpasync16(Kd + r * 16 + sch, Kg + i);
            cpasync16(Vd + r * 16 + sch, Vg + i);
        }
    };

    stage(0, 0);
    CP_COMMIT();

    for (int jt = 0; jt < NSEQ / 64; jt++) {
        if (jt + 1 < NSEQ / 64) stage(jt + 1, (jt + 1) & 1);
        CP_COMMIT();
        CP_WAIT1();
        __syncthreads();

        __nv_bfloat16* Ks = (__nv_bfloat16*)(smraw + (jt & 1) * 32768);
        __nv_bfloat16* Vs = Ks + 64 * 128;

        float S[8][4];
#pragma unroll
        for (int i = 0; i < 8; i++)
#pragma unroll
            for (int j = 0; j < 4; j++) S[i][j] = 0.f;
#pragma unroll
        for (int kb = 0; kb < 8; kb++) {
#pragma unroll
            for (int p = 0; p < 4; p++) {
                int r = p * 16 + rK_loc;
                int ch = 2 * kb + cK_bit;
                uint32_t b0, b1, b2, b3;
                ldsm4(b0, b1, b2, b3, Ks + r * 128 + ((ch ^ (r & 7)) << 3));
                uint32_t bb[2] = {b0, b1};
                mma16816(S[2 * p], qa[kb], bb);
                uint32_t bb2[2] = {b2, b3};
                mma16816(S[2 * p + 1], qa[kb], bb2);
            }
        }

        float m0 = -1e30f, m1 = -1e30f;
#pragma unroll
        for (int nb = 0; nb < 8; nb++) {
            m0 = fmaxf(m0, fmaxf(S[nb][0], S[nb][1]));
            m1 = fmaxf(m1, fmaxf(S[nb][2], S[nb][3]));
        }
        m0 = fmaxf(m0, __shfl_xor_sync(0xffffffffu, m0, 1));
        m0 = fmaxf(m0, __shfl_xor_sync(0xffffffffu, m0, 2));
        m1 = fmaxf(m1, __shfl_xor_sync(0xffffffffu, m1, 1));
        m1 = fmaxf(m1, __shfl_xor_sync(0xffffffffu, m1, 2));
        float mn0 = fmaxf(mrow0, m0), mn1 = fmaxf(mrow1, m1);
        bool inc = (mn0 > mrow0) | (mn1 > mrow1);
        if (__any_sync(0xffffffffu, inc)) {
            float scl0 = fast_exp(mrow0 - mn0), scl1 = fast_exp(mrow1 - mn1);
            lrow0 *= scl0; lrow1 *= scl1;
#pragma unroll
            for (int nb = 0; nb < 16; nb++) {
                O[nb][0] *= scl0; O[nb][1] *= scl0;
                O[nb][2] *= scl1; O[nb][3] *= scl1;
            }
        }
        mrow0 = mn0; mrow1 = mn1;
        float rs0 = 0.f, rs1 = 0.f;
#pragma unroll
        for (int nb = 0; nb < 8; nb++) {
            S[nb][0] = fast_exp(S[nb][0] - mn0);
            S[nb][1] = fast_exp(S[nb][1] - mn0);
            S[nb][2] = fast_exp(S[nb][2] - mn1);
            S[nb][3] = fast_exp(S[nb][3] - mn1);
            rs0 += S[nb][0] + S[nb][1];
            rs1 += S[nb][2] + S[nb][3];
        }
        rs0 += __shfl_xor_sync(0xffffffffu, rs0, 1);
        rs0 += __shfl_xor_sync(0xffffffffu, rs0, 2);
        rs1 += __shfl_xor_sync(0xffffffffu, rs1, 1);
        rs1 += __shfl_xor_sync(0xffffffffu, rs1, 2);
        lrow0 += rs0;
        lrow1 += rs1;

        uint32_t pa[4][4];
#pragma unroll
        for (int jb = 0; jb < 4; jb++) {
            pa[jb][0] = packbf2(S[2 * jb][0], S[2 * jb][1]);
            pa[jb][1] = packbf2(S[2 * jb][2], S[2 * jb][3]);
            pa[jb][2] = packbf2(S[2 * jb + 1][0], S[2 * jb + 1][1]);
            pa[jb][3] = packbf2(S[2 * jb + 1][2], S[2 * jb + 1][3]);
        }

#pragma unroll
        for (int jb = 0; jb < 4; jb++) {
            int r = jb * 16 + rV_loc;
#pragma unroll
            for (int cp = 0; cp < 8; cp++) {
                int ch = 2 * cp + cV_bit;
                uint32_t b0, b1, b2, b3;
                ldsm4t(b0, b1, b2, b3, Vs + r * 128 + ((ch ^ (r & 7)) << 3));
                uint32_t bb[2] = {b0, b1};
                mma16816(O[2 * cp], pa[jb], bb);
                uint32_t bb2[2] = {b2, b3};
                mma16816(O[2 * cp + 1], pa[jb], bb2);
            }
        }
        __syncthreads();
    }

    // ---- epilogue: stage out[c][n] patch in smem, coalesced global write ----
    {
        float inv0 = 1.f / lrow0, inv1 = 1.f / lrow1;
        int row0 = w * 16 + g, row1 = row0 + 8;
        const float* nvp0 = gnv + ((size_t)(b * NSEQ) + q0 + row0) * nv_ld;
        const float* nvp1 = gnv + ((size_t)(b * NSEQ) + q0 + row1) * nv_ld;
#pragma unroll
        for (int nb = 0; nb < 16; nb++) {
            int c = nb * 8 + 2 * tc;
            float2 nv0 = *(const float2*)(nvp0 + c);
            float2 nv1 = *(const float2*)(nvp1 + c);
            OutS[c * OPITCH + row0] = fmaf(THITA, O[nb][0] * inv0, nv0.x);
            OutS[(c + 1) * OPITCH + row0] = fmaf(THITA, O[nb][1] * inv0, nv0.y);
            OutS[c * OPITCH + row1] = fmaf(THITA, O[nb][2] * inv1, nv1.x);
            OutS[(c + 1) * OPITCH + row1] = fmaf(THITA, O[nb][3] * inv1, nv1.y);
        }
    }
    __syncthreads();
    {
        float* ob = out + (size_t)b * CH * NSEQ + q0;
        for (int i = tid; i < 128 * 128 / 4; i += 256) {
            int idx = i * 4;
            int c = idx >> 7, nl = idx & 127;
            float4 v = *(const float4*)(OutS + c * OPITCH + nl);
            *(float4*)(ob + (size_t)c * NSEQ + nl) = v;
        }
    }
}

// ---------------- host launch --------------------------------------------------
extern "C" void kernel_launch(void* const* d_in, const int* in_sizes, int n_in,
                              void* d_out, int out_size) {
    const float* event = (const float*)d_in[0];
    const float* W[12];
    const float* Bv[12];
    for (int i = 0; i < 12; i++) {
        W[i] = (const float*)d_in[1 + 2 * i];
        Bv[i] = (const float*)d_in[2 + 2 * i];
    }
    // 0 neighbor, 1 pro_key, 2 pro_val, 3 lat_key, 4 lat_val, 5 tmp1,
    // 6 now1, 7 now_key, 8 now_val, 9 q, 10 k, 11 v

    float *nowval, *bc1, *bc2;
    __nv_bfloat16 *neigh, *keycat, *valcat, *keyn, *valn, *nowfb, *nowkey, *qb, *kb, *vb;
    __nv_bfloat16 *wb1, *wb2, *wbt, *wbnk, *wbq, *wbk, *wbv, *w8hi, *w8lo;
    cudaGetSymbolAddress((void**)&nowval, g_nowval);
    cudaGetSymbolAddress((void**)&neigh, g_neigh);
    cudaGetSymbolAddress((void**)&keycat, g_keycat);
    cudaGetSymbolAddress((void**)&valcat, g_valcat);
    cudaGetSymbolAddress((void**)&keyn, g_keyn);
    cudaGetSymbolAddress((void**)&valn, g_valn);
    cudaGetSymbolAddress((void**)&nowfb, g_nowfb);
    cudaGetSymbolAddress((void**)&nowkey, g_nowkey);
    cudaGetSymbolAddress((void**)&qb, g_qb);
    cudaGetSymbolAddress((void**)&kb, g_kb);
    cudaGetSymbolAddress((void**)&vb, g_vb);
    cudaGetSymbolAddress((void**)&wb1, g_wb1);
    cudaGetSymbolAddress((void**)&wb2, g_wb2);
    cudaGetSymbolAddress((void**)&wbt, g_wbt);
    cudaGetSymbolAddress((void**)&wbnk, g_wbnk);
    cudaGetSymbolAddress((void**)&wbq, g_wbq);
    cudaGetSymbolAddress((void**)&wbk, g_wbk);
    cudaGetSymbolAddress((void**)&wbv, g_wbv);
    cudaGetSymbolAddress((void**)&w8hi, g_w8hi);
    cudaGetSymbolAddress((void**)&w8lo, g_w8lo);
    cudaGetSymbolAddress((void**)&bc1, g_bc1);
    cudaGetSymbolAddress((void**)&bc2, g_bc2);

    cudaFuncSetAttribute(attn_kernel, cudaFuncAttributeMaxDynamicSharedMemorySize, ATTN_SMEM);
    cudaFuncSetAttribute(gemm_nowval, cudaFuncAttributeMaxDynamicSharedMemorySize, NV_SMEM);

    prep_w_kernel<<<640, 256>>>(W[1], W[3], W[2], W[4], W[5], W[7], W[9], W[10], W[11], W[8],
                                Bv[1], Bv[3], Bv[2], Bv[4]);
    neighbor_kernel<<<PIX * 32 / 256, 256>>>(event, W[0], Bv[0], neigh);
    nowf_kernel<<<PIX * 16 / 256, 256>>>(event, W[6], Bv[6], nowfb);

    dim3 gA(PIX / 128, 2);   // N = 256
    dim3 gB(PIX / 128, 1);   // N = 128
    gemm_bf16<<<gA, 256>>>(neigh, 256, wb1, bc1, keycat, 256, 128);        // [pro_key|lat_key]
    gemm_bf16<<<gA, 256>>>(neigh + 128, 256, wb2, bc2, valcat, 256, 128);  // [pro_val|lat_val]
    gemm_bf16<<<gB, 256>>>(keycat, 256, wbt, Bv[5], keyn, 128, 256);       // key_n
    gemm_bf16<<<gB, 256>>>(valcat, 256, wbt, Bv[5], valn, 128, 256);       // val_n
    gemm_bf16<<<gB, 256>>>(nowfb, 128, wbnk, Bv[7], nowkey, 128, 128);     // now_key
    gemm_nowval<<<PIX / 128, 256, NV_SMEM>>>(event, W[6], Bv[6], w8hi, w8lo, Bv[8], nowval);
    gemm_bf16<<<gB, 256>>>(keyn, 128, wbq, Bv[9], qb, 128, 128);           // q
    gemm_bf16<<<gB, 256>>>(nowkey, 128, wbk, Bv[10], kb, 128, 128);        // k
    gemm_bf16<<<gB, 256>>>(valn, 128, wbv, Bv[11], vb, 128, 128);          // v

    attn_kernel<<<dim3(NSEQ / 128, BSZ), 256, ATTN_SMEM>>>(qb, kb, vb, nowval, 128,
                                                           (float*)d_out);
}

// round 7
// speedup vs baseline: 9.7336x; 1.5013x over previous
#include <cuda_runtime.h>
#include <cuda_bf16.h>
#include <cstdint>

// Problem constants
#define PIX 16384        // B*H*W
#define NSEQ 4096        // H*W
#define BSZ 4
#define CH 128
#define THITA 1e-4f

typedef __nv_bfloat16 bf16;

// ---------------- scratch (device globals; no allocation allowed) -------------
__device__ float g_nowval[PIX * 128];
__device__ bf16 g_qb[PIX * 128];
__device__ bf16 g_kb[PIX * 128];
__device__ bf16 g_vb[PIX * 128];
// bf16 weights
__device__ bf16 g_wb1[256 * 128];   // [w_pro_key ; w_lat_key]
__device__ bf16 g_wb2[256 * 128];   // [w_pro_val ; w_lat_val]
__device__ bf16 g_wbt[128 * 256];   // w_tmp1
__device__ bf16 g_wbnk[128 * 128];  // w_now_key
__device__ bf16 g_wbq[128 * 128];
__device__ bf16 g_wbk[128 * 128];
__device__ bf16 g_wbv[128 * 128];
__device__ bf16 g_w8hi[128 * 128];  // w_now_val split hi
__device__ bf16 g_w8lo[128 * 128];  // w_now_val split lo
__device__ float g_bc1[256];
__device__ float g_bc2[256];

// ---------------- weight prep: fp32 -> bf16 (+ concats + now_val split) ------
__global__ void __launch_bounds__(256) prep_w_kernel(
    const float* __restrict__ wpk, const float* __restrict__ wlk,
    const float* __restrict__ wpv, const float* __restrict__ wlv,
    const float* __restrict__ wt,  const float* __restrict__ wnk,
    const float* __restrict__ wq,  const float* __restrict__ wk,
    const float* __restrict__ wv,  const float* __restrict__ wnv,
    const float* __restrict__ bpk, const float* __restrict__ blk,
    const float* __restrict__ bpv, const float* __restrict__ blv) {
    int i = blockIdx.x * blockDim.x + threadIdx.x;   // 0..163839
    if (i < 32768) {
        g_wb1[i] = __float2bfloat16(i < 16384 ? wpk[i] : wlk[i - 16384]);
        g_wb2[i] = __float2bfloat16(i < 16384 ? wpv[i] : wlv[i - 16384]);
        g_wbt[i] = __float2bfloat16(wt[i]);
    } else if (i < 49152) {
        int j = i - 32768;
        if (j < 16384) {
            g_wbnk[j] = __float2bfloat16(wnk[j]);
            float v = wnv[j];
            bf16 h = __float2bfloat16(v);
            g_w8hi[j] = h;
            g_w8lo[j] = __float2bfloat16(v - __bfloat162float(h));
        }
    } else if (i < 65536) {
        int j = i - 49152;
        g_wbq[j] = __float2bfloat16(wq[j]);
        g_wbk[j] = __float2bfloat16(wk[j]);
        g_wbv[j] = __float2bfloat16(wv[j]);
    }
    if (i < 256) {
        g_bc1[i] = i < 128 ? bpk[i] : blk[i - 128];
        g_bc2[i] = i < 128 ? bpv[i] : blv[i - 128];
    }
}

// ---------------- mma / ldmatrix helpers --------------------------------------
__device__ __forceinline__ void mma16816(float* c, const uint32_t* a, const uint32_t* b) {
    asm volatile(
        "mma.sync.aligned.m16n8k16.row.col.f32.bf16.bf16.f32 "
        "{%0,%1,%2,%3}, {%4,%5,%6,%7}, {%8,%9}, {%0,%1,%2,%3};"
        : "+f"(c[0]), "+f"(c[1]), "+f"(c[2]), "+f"(c[3])
        : "r"(a[0]), "r"(a[1]), "r"(a[2]), "r"(a[3]), "r"(b[0]), "r"(b[1]));
}

__device__ __forceinline__ void ldsm4(uint32_t& r0, uint32_t& r1, uint32_t& r2, uint32_t& r3,
                                      const void* p) {
    uint32_t addr = (uint32_t)__cvta_generic_to_shared(p);
    asm volatile("ldmatrix.sync.aligned.m8n8.x4.shared.b16 {%0,%1,%2,%3}, [%4];"
                 : "=r"(r0), "=r"(r1), "=r"(r2), "=r"(r3) : "r"(addr));
}

__device__ __forceinline__ void ldsm4t(uint32_t& r0, uint32_t& r1, uint32_t& r2, uint32_t& r3,
                                       const void* p) {
    uint32_t addr = (uint32_t)__cvta_generic_to_shared(p);
    asm volatile("ldmatrix.sync.aligned.m8n8.x4.trans.shared.b16 {%0,%1,%2,%3}, [%4];"
                 : "=r"(r0), "=r"(r1), "=r"(r2), "=r"(r3) : "r"(addr));
}

__device__ __forceinline__ uint32_t packbf2(float lo, float hi) {
    uint32_t d;
    asm("cvt.rn.bf16x2.f32 %0, %1, %2;" : "=r"(d) : "f"(hi), "f"(lo));
    return d;
}

__device__ __forceinline__ void cpasync16(void* dst, const void* src) {
    uint32_t d = (uint32_t)__cvta_generic_to_shared(dst);
    asm volatile("cp.async.cg.shared.global [%0], [%1], 16;" :: "r"(d), "l"(src));
}
#define CP_COMMIT() asm volatile("cp.async.commit_group;")
#define CP_WAIT0()  asm volatile("cp.async.wait_group 0;")
#define CP_WAIT1()  asm volatile("cp.async.wait_group 1;")

// ============ fused conv chain =================================================
// Canonical activation/weight smem layout: [kblock][128 rows][64 ch], each
// 64-ch row = 8 16B chunks, chunk ch stored at (ch ^ (row&7)). Subtile = 8192
// bf16 elems (16KB). All stages read/write this layout.

// One GEMM stage: out128 = relu(W[128][K] @ in[128][K] + bias). Out to smem
// (canonical layout) or global (row-major, ld=128).
template <int K>
__device__ __forceinline__ void stage_gemm(
    const bf16* __restrict__ inb,    // smem, K/64 subtiles
    const bf16* __restrict__ wg,     // global [128][K]
    const float* __restrict__ bias,  // global [128]
    bf16* __restrict__ wbuf,         // smem W buffer (K/64 subtiles)
    bf16* __restrict__ outb,         // smem out (2 subtiles) or nullptr
    bf16* __restrict__ outg,         // global out base or nullptr
    int m0, int tid) {
    const int lane = tid & 31, wid = tid >> 5;
    const int wm = (wid & 1) * 64, wn = (wid >> 1) * 32;
    const int g = lane >> 2, tc = lane & 3;
    const int rA_loc = ((lane >> 3) & 1) * 8 + (lane & 7);
    const int cA_bit = (lane >> 4) & 1;
    const int rB_loc = ((lane >> 4) & 1) * 8 + (lane & 7);
    const int cB_bit = (lane >> 3) & 1;
    constexpr int CPR = K >> 3;          // 16B chunks per weight row

    // stage W into smem (canonical layout) via cp.async
#pragma unroll
    for (int i = tid; i < 128 * CPR; i += 256) {
        int n = i / CPR, ck = i % CPR;
        int kb = ck >> 3, c8 = ck & 7;
        cpasync16((uint4*)wbuf + kb * 1024 + n * 8 + (c8 ^ (n & 7)),
                  (const uint4*)wg + i);
    }
    CP_COMMIT();
    CP_WAIT0();
    __syncthreads();

    float acc[4][4][4];
#pragma unroll
    for (int i = 0; i < 4; i++)
#pragma unroll
        for (int j = 0; j < 4; j++)
#pragma unroll
            for (int l = 0; l < 4; l++) acc[i][j][l] = 0.f;

#pragma unroll
    for (int kb = 0; kb < K / 64; kb++) {
        const bf16* As = inb + kb * 8192;
        const bf16* Bs = wbuf + kb * 8192;
#pragma unroll
        for (int ks = 0; ks < 4; ks++) {
            uint32_t a[4][4], bf[2][4];
#pragma unroll
            for (int mi = 0; mi < 4; mi++) {
                int r = wm + mi * 16 + rA_loc;
                int ch = 2 * ks + cA_bit;
                ldsm4(a[mi][0], a[mi][1], a[mi][2], a[mi][3],
                      As + r * 64 + ((ch ^ (r & 7)) << 3));
            }
#pragma unroll
            for (int ni = 0; ni < 2; ni++) {
                int r = wn + ni * 16 + rB_loc;
                int ch = 2 * ks + cB_bit;
                ldsm4(bf[ni][0], bf[ni][1], bf[ni][2], bf[ni][3],
                      Bs + r * 64 + ((ch ^ (r & 7)) << 3));
            }
#pragma unroll
            for (int mi = 0; mi < 4; mi++)
#pragma unroll
                for (int ni = 0; ni < 2; ni++) {
                    uint32_t b0[2] = {bf[ni][0], bf[ni][1]};
                    mma16816(acc[mi][2 * ni], a[mi], b0);
                    uint32_t b1[2] = {bf[ni][2], bf[ni][3]};
                    mma16816(acc[mi][2 * ni + 1], a[mi], b1);
                }
        }
    }

    // epilogue
#pragma unroll
    for (int mi = 0; mi < 4; mi++) {
        int r0 = wm + mi * 16 + g;
#pragma unroll
        for (int n8 = 0; n8 < 4; n8++) {
            int c = wn + n8 * 8 + 2 * tc;
            float2 bv = *(const float2*)(bias + c);
            uint32_t p0 = packbf2(fmaxf(acc[mi][n8][0] + bv.x, 0.f),
                                  fmaxf(acc[mi][n8][1] + bv.y, 0.f));
            uint32_t p1 = packbf2(fmaxf(acc[mi][n8][2] + bv.x, 0.f),
                                  fmaxf(acc[mi][n8][3] + bv.y, 0.f));
            if (outb) {
                int kb_o = c >> 6, cl = c & 63, chk = cl >> 3, off = cl & 7;
                bf16* base = outb + kb_o * 8192;
                *(uint32_t*)(base + r0 * 64 + ((chk ^ (r0 & 7)) << 3) + off) = p0;
                int r1 = r0 + 8;
                *(uint32_t*)(base + r1 * 64 + ((chk ^ (r1 & 7)) << 3) + off) = p1;
            } else {
                *(uint32_t*)(outg + (size_t)(m0 + r0) * 128 + c) = p0;
                *(uint32_t*)(outg + (size_t)(m0 + r0 + 8) * 128 + c) = p1;
            }
        }
    }
    __syncthreads();   // out visible / W free for next stage
}

#define FUSED_SMEM (65536 + 65536 + 32768 + 65536)   // A,B,C,W = 229376 B

__global__ void __launch_bounds__(256, 1) fused_conv_kernel(
    const float* __restrict__ event,
    const float* __restrict__ w0, const float* __restrict__ b0,
    const float* __restrict__ w6, const float* __restrict__ b6,
    const bf16* __restrict__ wb1, const float* __restrict__ bc1,
    const bf16* __restrict__ wb2, const float* __restrict__ bc2,
    const bf16* __restrict__ wbt, const float* __restrict__ bt,
    const bf16* __restrict__ wbnk, const float* __restrict__ bnk,
    const bf16* __restrict__ wbq, const float* __restrict__ bq,
    const bf16* __restrict__ wbk, const float* __restrict__ bk,
    const bf16* __restrict__ wbv, const float* __restrict__ bv,
    bf16* __restrict__ qb, bf16* __restrict__ kb_, bf16* __restrict__ vb) {
    extern __shared__ char sm[];
    bf16* A = (bf16*)sm;              // 4 subtiles (256 ch)
    bf16* B = (bf16*)(sm + 65536);    // 4 subtiles
    bf16* C = (bf16*)(sm + 131072);   // 2 subtiles
    bf16* W = (bf16*)(sm + 163840);   // 4 subtiles
    const int tid = threadIdx.x;
    const int m0 = blockIdx.x * 128;
    const float* ev = event + (size_t)(m0 >> 12) * 6 * NSEQ + (m0 & 4095);

    // ---- neigh (K=4 conv) -> A, 256 ch ----
    for (int i = tid; i < 4096; i += 256) {
        int r = i >> 5, ck = i & 31;
        float x0 = ev[r], x1 = ev[NSEQ + r], x2 = ev[4 * NSEQ + r], x3 = ev[5 * NSEQ + r];
        uint32_t pk[4];
#pragma unroll
        for (int j = 0; j < 4; j++) {
            int c0 = ck * 8 + 2 * j, c1 = c0 + 1;
            float v0 = fmaf(w0[c0 * 4 + 3], x3, fmaf(w0[c0 * 4 + 2], x2,
                       fmaf(w0[c0 * 4 + 1], x1, fmaf(w0[c0 * 4], x0, b0[c0]))));
            float v1 = fmaf(w0[c1 * 4 + 3], x3, fmaf(w0[c1 * 4 + 2], x2,
                       fmaf(w0[c1 * 4 + 1], x1, fmaf(w0[c1 * 4], x0, b0[c1]))));
            pk[j] = packbf2(fmaxf(v0, 0.f), fmaxf(v1, 0.f));
        }
        ((uint4*)A)[(ck >> 3) * 1024 + r * 8 + ((ck & 7) ^ (r & 7))] =
            make_uint4(pk[0], pk[1], pk[2], pk[3]);
    }
    __syncthreads();

    // key path: keycat = [wb1 @ A_lo] (256ch) -> B ; keyn -> C ; q -> global
    stage_gemm<128>(A, wb1, bc1, W, B, nullptr, m0, tid);
    stage_gemm<128>(A, wb1 + 128 * 128, bc1 + 128, W, B + 2 * 8192, nullptr, m0, tid);
    stage_gemm<256>(B, wbt, bt, W, C, nullptr, m0, tid);
    stage_gemm<128>(C, wbq, bq, W, nullptr, qb, m0, tid);

    // val path: valcat from A_hi -> B ; valn -> C ; v -> global
    stage_gemm<128>(A + 2 * 8192, wb2, bc2, W, B, nullptr, m0, tid);
    stage_gemm<128>(A + 2 * 8192, wb2 + 128 * 128, bc2 + 128, W, B + 2 * 8192, nullptr, m0, tid);
    stage_gemm<256>(B, wbt, bt, W, C, nullptr, m0, tid);
    stage_gemm<128>(C, wbv, bv, W, nullptr, vb, m0, tid);

    // now path: nowf (K=2 conv) -> A kb0-1 ; nowkey -> C ; k -> global
    for (int i = tid; i < 2048; i += 256) {
        int r = i >> 4, ck = i & 15;
        float x = ev[2 * NSEQ + r], y = ev[3 * NSEQ + r];
        uint32_t pk[4];
#pragma unroll
        for (int j = 0; j < 4; j++) {
            int c0 = ck * 8 + 2 * j, c1 = c0 + 1;
            float v0 = fmaxf(fmaf(w6[c0 * 2 + 1], y, fmaf(w6[c0 * 2], x, b6[c0])), 0.f);
            float v1 = fmaxf(fmaf(w6[c1 * 2 + 1], y, fmaf(w6[c1 * 2], x, b6[c1])), 0.f);
            pk[j] = packbf2(v0, v1);
        }
        ((uint4*)A)[(ck >> 3) * 1024 + r * 8 + ((ck & 7) ^ (r & 7))] =
            make_uint4(pk[0], pk[1], pk[2], pk[3]);
    }
    __syncthreads();
    stage_gemm<128>(A, wbnk, bnk, W, C, nullptr, m0, tid);
    stage_gemm<128>(C, wbk, bk, W, nullptr, kb_, m0, tid);
}

// ---------------- now_val: fused nowf (K=2, fp32 on the fly) + split-bf16 GEMM
#define NV_SMEM (65536 + 1024 + 1024 + 512)

__global__ void __launch_bounds__(256) gemm_nowval(
    const float* __restrict__ event,
    const float* __restrict__ w6, const float* __restrict__ b6,
    const bf16* __restrict__ w8hi, const bf16* __restrict__ w8lo,
    const float* __restrict__ b8,
    float* __restrict__ out) {
    extern __shared__ char sm[];
    bf16* Ah = (bf16*)sm;            // [128][64] swizzled
    bf16* Al = Ah + 128 * 64;
    bf16* Bh = Al + 128 * 64;
    bf16* Bl = Bh + 128 * 64;
    float* x2s = (float*)(sm + 65536);
    float* w6s = x2s + 256;
    float* b6s = w6s + 256;

    const int tid = threadIdx.x, lane = tid & 31, wid = tid >> 5;
    const int m0 = blockIdx.x * 128;
    const int wm = (wid & 1) * 64, wn = (wid >> 1) * 32;
    const int g = lane >> 2, tc = lane & 3;
    const int rA_loc = ((lane >> 3) & 1) * 8 + (lane & 7);
    const int cA_bit = (lane >> 4) & 1;
    const int rB_loc = ((lane >> 4) & 1) * 8 + (lane & 7);
    const int cB_bit = (lane >> 3) & 1;

    {
        int bb = m0 >> 12;
        const float* e = event + (size_t)bb * 6 * NSEQ + (m0 & 4095);
        if (tid < 128) {
            x2s[2 * tid] = e[2 * NSEQ + tid];
            x2s[2 * tid + 1] = e[3 * NSEQ + tid];
            b6s[tid] = b6[tid];
        } else {
            int j = tid - 128;
            ((float2*)w6s)[j] = ((const float2*)w6)[j];
        }
    }
    __syncthreads();

    float acc[4][4][4];
#pragma unroll
    for (int i = 0; i < 4; i++)
#pragma unroll
        for (int j = 0; j < 4; j++)
#pragma unroll
            for (int l = 0; l < 4; l++) acc[i][j][l] = 0.f;

    for (int k0 = 0; k0 < 128; k0 += 64) {
#pragma unroll
        for (int i = 0; i < 4; i++) {
            int li = tid + i * 256;
            int r = li >> 3, cch = li & 7;
            float x0 = x2s[2 * r], x1 = x2s[2 * r + 1];
            uint4 hq, lq;
            bf16* hp = (bf16*)&hq;
            bf16* lp = (bf16*)&lq;
#pragma unroll
            for (int j = 0; j < 8; j++) {
                int k = k0 + cch * 8 + j;
                float v = fmaxf(fmaf(w6s[2 * k + 1], x1, fmaf(w6s[2 * k], x0, b6s[k])), 0.f);
                bf16 h = __float2bfloat16(v);
                hp[j] = h;
                lp[j] = __float2bfloat16(v - __bfloat162float(h));
            }
            int sidx = r * 8 + (cch ^ (r & 7));
            ((uint4*)Ah)[sidx] = hq;
            ((uint4*)Al)[sidx] = lq;
            ((uint4*)Bh)[sidx] = *(const uint4*)(w8hi + (size_t)r * 128 + k0 + cch * 8);
            ((uint4*)Bl)[sidx] = *(const uint4*)(w8lo + (size_t)r * 128 + k0 + cch * 8);
        }
        __syncthreads();
#pragma unroll
        for (int ks = 0; ks < 4; ks++) {
            uint32_t ah[4][4], al[4][4], bh[2][4], bl[2][4];
#pragma unroll
            for (int mi = 0; mi < 4; mi++) {
                int r = wm + mi * 16 + rA_loc;
                int ch = 2 * ks + cA_bit;
                int off = r * 64 + ((ch ^ (r & 7)) << 3);
                ldsm4(ah[mi][0], ah[mi][1], ah[mi][2], ah[mi][3], Ah + off);
                ldsm4(al[mi][0], al[mi][1], al[mi][2], al[mi][3], Al + off);
            }
#pragma unroll
            for (int ni = 0; ni < 2; ni++) {
                int r = wn + ni * 16 + rB_loc;
                int ch = 2 * ks + cB_bit;
                int off = r * 64 + ((ch ^ (r & 7)) << 3);
                ldsm4(bh[ni][0], bh[ni][1], bh[ni][2], bh[ni][3], Bh + off);
                ldsm4(bl[ni][0], bl[ni][1], bl[ni][2], bl[ni][3], Bl + off);
            }
#pragma unroll
            for (int mi = 0; mi < 4; mi++)
#pragma unroll
                for (int ni = 0; ni < 2; ni++) {
                    uint32_t h0[2] = {bh[ni][0], bh[ni][1]};
                    uint32_t h1[2] = {bh[ni][2], bh[ni][3]};
                    uint32_t l0[2] = {bl[ni][0], bl[ni][1]};
                    uint32_t l1[2] = {bl[ni][2], bl[ni][3]};
                    mma16816(acc[mi][2 * ni], ah[mi], h0);
                    mma16816(acc[mi][2 * ni + 1], ah[mi], h1);
                    mma16816(acc[mi][2 * ni], ah[mi], l0);
                    mma16816(acc[mi][2 * ni + 1], ah[mi], l1);
                    mma16816(acc[mi][2 * ni], al[mi], h0);
                    mma16816(acc[mi][2 * ni + 1], al[mi], h1);
                }
        }
        __syncthreads();
    }
#pragma unroll
    for (int mi = 0; mi < 4; mi++) {
        int r0 = m0 + wm + mi * 16 + g;
#pragma unroll
        for (int n8 = 0; n8 < 4; n8++) {
            int c = wn + n8 * 8 + 2 * tc;
            float2 bv = *(const float2*)(b8 + c);
            float2 v01, v23;
            v01.x = fmaxf(acc[mi][n8][0] + bv.x, 0.f);
            v01.y = fmaxf(acc[mi][n8][1] + bv.y, 0.f);
            v23.x = fmaxf(acc[mi][n8][2] + bv.x, 0.f);
            v23.y = fmaxf(acc[mi][n8][3] + bv.y, 0.f);
            *(float2*)(out + (size_t)r0 * 128 + c) = v01;
            *(float2*)(out + (size_t)(r0 + 8) * 128 + c) = v23;
        }
    }
}

// ---------------- fast exp (Schraudolph); args <= 0, clamp avoids wraparound --
__device__ __forceinline__ float fast_exp(float x) {
    x = fmaxf(x, -80.f);
    int i = (int)(fmaf(x, 12102203.0f, 1064866805.0f));
    return __int_as_float(i);
}

// ---------------- flash attention, bf16 HMMA, BM=128 BN=64, 2-stage cp.async --
#define OPITCH 132
#define ATTN_SMEM (128 * OPITCH * 4)   // 67584 >= 2 stages * 32KB KV

__global__ void __launch_bounds__(256, 1) attn_kernel(
    const bf16* __restrict__ gq,
    const bf16* __restrict__ gk,
    const bf16* __restrict__ gv,
    const float* __restrict__ gnv, int nv_ld,
    float* __restrict__ out) {
    extern __shared__ char smraw[];
    float* OutS = (float*)smraw;                   // reused post-loop, [128][OPITCH]

    const int tid = threadIdx.x;
    const int lane = tid & 31, w = tid >> 5;
    const int g = lane >> 2, tc = lane & 3;
    const int b = blockIdx.y;
    const int q0 = blockIdx.x * 128;

    uint32_t qa[8][4];
    {
        const bf16* Qb = gq + ((size_t)(b * NSEQ) + q0 + w * 16) * CH;
#pragma unroll
        for (int kb = 0; kb < 8; kb++) {
            qa[kb][0] = *(const uint32_t*)(Qb + (size_t)g * CH + kb * 16 + 2 * tc);
            qa[kb][1] = *(const uint32_t*)(Qb + (size_t)(g + 8) * CH + kb * 16 + 2 * tc);
            qa[kb][2] = *(const uint32_t*)(Qb + (size_t)g * CH + kb * 16 + 8 + 2 * tc);
            qa[kb][3] = *(const uint32_t*)(Qb + (size_t)(g + 8) * CH + kb * 16 + 8 + 2 * tc);
        }
    }

    float O[16][4];
#pragma unroll
    for (int i = 0; i < 16; i++)
#pragma unroll
        for (int j = 0; j < 4; j++) O[i][j] = 0.f;
    float mrow0 = -1e30f, mrow1 = -1e30f, lrow0 = 0.f, lrow1 = 0.f;

    const int rK_loc = ((lane >> 4) & 1) * 8 + (lane & 7);
    const int cK_bit = (lane >> 3) & 1;
    const int rV_loc = ((lane >> 3) & 1) * 8 + (lane & 7);
    const int cV_bit = lane >> 4;

    const bf16* Kgb = gk + (size_t)b * NSEQ * CH;
    const bf16* Vgb = gv + (size_t)b * NSEQ * CH;

    auto stage = [&](int jt, int s) {
        const uint4* Kg = (const uint4*)(Kgb + (size_t)jt * 64 * CH);
        const uint4* Vg = (const uint4*)(Vgb + (size_t)jt * 64 * CH);
        uint4* Kd = (uint4*)(smraw + s * 32768);
        uint4* Vd = Kd + 1024;
#pragma unroll
        for (int i = tid; i < 1024; i += 256) {
            int r = i >> 4, ch = i & 15, sch = ch ^ (r & 7);
            cpasync16(Kd + r * 16 + sch, Kg + i);
            cpasync16(Vd + r * 16 + sch, Vg + i);
        }
    };

    stage(0, 0);
    CP_COMMIT();

    for (int jt = 0; jt < NSEQ / 64; jt++) {
        if (jt + 1 < NSEQ / 64) stage(jt + 1, (jt + 1) & 1);
        CP_COMMIT();
        CP_WAIT1();
        __syncthreads();

        bf16* Ks = (bf16*)(smraw + (jt & 1) * 32768);
        bf16* Vs = Ks + 64 * 128;

        float S[8][4];
#pragma unroll
        for (int i = 0; i < 8; i++)
#pragma unroll
            for (int j = 0; j < 4; j++) S[i][j] = 0.f;
#pragma unroll
        for (int kb = 0; kb < 8; kb++) {
#pragma unroll
            for (int p = 0; p < 4; p++) {
                int r = p * 16 + rK_loc;
                int ch = 2 * kb + cK_bit;
                uint32_t b0, b1, b2, b3;
                ldsm4(b0, b1, b2, b3, Ks + r * 128 + ((ch ^ (r & 7)) << 3));
                uint32_t bb[2] = {b0, b1};
                mma16816(S[2 * p], qa[kb], bb);
                uint32_t bb2[2] = {b2, b3};
                mma16816(S[2 * p + 1], qa[kb], bb2);
            }
        }

        float m0 = -1e30f, m1 = -1e30f;
#pragma unroll
        for (int nb = 0; nb < 8; nb++) {
            m0 = fmaxf(m0, fmaxf(S[nb][0], S[nb][1]));
            m1 = fmaxf(m1, fmaxf(S[nb][2], S[nb][3]));
        }
        m0 = fmaxf(m0, __shfl_xor_sync(0xffffffffu, m0, 1));
        m0 = fmaxf(m0, __shfl_xor_sync(0xffffffffu, m0, 2));
        m1 = fmaxf(m1, __shfl_xor_sync(0xffffffffu, m1, 1));
        m1 = fmaxf(m1, __shfl_xor_sync(0xffffffffu, m1, 2));
        float mn0 = fmaxf(mrow0, m0), mn1 = fmaxf(mrow1, m1);
        bool inc = (mn0 > mrow0) | (mn1 > mrow1);
        if (__any_sync(0xffffffffu, inc)) {
            float scl0 = fast_exp(mrow0 - mn0), scl1 = fast_exp(mrow1 - mn1);
            lrow0 *= scl0; lrow1 *= scl1;
#pragma unroll
            for (int nb = 0; nb < 16; nb++) {
                O[nb][0] *= scl0; O[nb][1] *= scl0;
                O[nb][2] *= scl1; O[nb][3] *= scl1;
            }
        }
        mrow0 = mn0; mrow1 = mn1;
        float rs0 = 0.f, rs1 = 0.f;
#pragma unroll
        for (int nb = 0; nb < 8; nb++) {
            S[nb][0] = fast_exp(S[nb][0] - mn0);
            S[nb][1] = fast_exp(S[nb][1] - mn0);
            S[nb][2] = fast_exp(S[nb][2] - mn1);
            S[nb][3] = fast_exp(S[nb][3] - mn1);
            rs0 += S[nb][0] + S[nb][1];
            rs1 += S[nb][2] + S[nb][3];
        }
        rs0 += __shfl_xor_sync(0xffffffffu, rs0, 1);
        rs0 += __shfl_xor_sync(0xffffffffu, rs0, 2);
        rs1 += __shfl_xor_sync(0xffffffffu, rs1, 1);
        rs1 += __shfl_xor_sync(0xffffffffu, rs1, 2);
        lrow0 += rs0;
        lrow1 += rs1;

        uint32_t pa[4][4];
#pragma unroll
        for (int jb = 0; jb < 4; jb++) {
            pa[jb][0] = packbf2(S[2 * jb][0], S[2 * jb][1]);
            pa[jb][1] = packbf2(S[2 * jb][2], S[2 * jb][3]);
            pa[jb][2] = packbf2(S[2 * jb + 1][0], S[2 * jb + 1][1]);
            pa[jb][3] = packbf2(S[2 * jb + 1][2], S[2 * jb + 1][3]);
        }

#pragma unroll
        for (int jb = 0; jb < 4; jb++) {
            int r = jb * 16 + rV_loc;
#pragma unroll
            for (int cp = 0; cp < 8; cp++) {
                int ch = 2 * cp + cV_bit;
                uint32_t b0, b1, b2, b3;
                ldsm4t(b0, b1, b2, b3, Vs + r * 128 + ((ch ^ (r & 7)) << 3));
                uint32_t bb[2] = {b0, b1};
                mma16816(O[2 * cp], pa[jb], bb);
                uint32_t bb2[2] = {b2, b3};
                mma16816(O[2 * cp + 1], pa[jb], bb2);
            }
        }
        __syncthreads();
    }

    // ---- epilogue: stage out[c][n] patch in smem, coalesced global write ----
    {
        float inv0 = 1.f / lrow0, inv1 = 1.f / lrow1;
        int row0 = w * 16 + g, row1 = row0 + 8;
        const float* nvp0 = gnv + ((size_t)(b * NSEQ) + q0 + row0) * nv_ld;
        const float* nvp1 = gnv + ((size_t)(b * NSEQ) + q0 + row1) * nv_ld;
#pragma unroll
        for (int nb = 0; nb < 16; nb++) {
            int c = nb * 8 + 2 * tc;
            float2 nv0 = *(const float2*)(nvp0 + c);
            float2 nv1 = *(const float2*)(nvp1 + c);
            OutS[c * OPITCH + row0] = fmaf(THITA, O[nb][0] * inv0, nv0.x);
            OutS[(c + 1) * OPITCH + row0] = fmaf(THITA, O[nb][1] * inv0, nv0.y);
            OutS[c * OPITCH + row1] = fmaf(THITA, O[nb][2] * inv1, nv1.x);
            OutS[(c + 1) * OPITCH + row1] = fmaf(THITA, O[nb][3] * inv1, nv1.y);
        }
    }
    __syncthreads();
    {
        float* ob = out + (size_t)b * CH * NSEQ + q0;
        for (int i = tid; i < 128 * 128 / 4; i += 256) {
            int idx = i * 4;
            int c = idx >> 7, nl = idx & 127;
            float4 v = *(const float4*)(OutS + c * OPITCH + nl);
            *(float4*)(ob + (size_t)c * NSEQ + nl) = v;
        }
    }
}

// ---------------- host launch --------------------------------------------------
extern "C" void kernel_launch(void* const* d_in, const int* in_sizes, int n_in,
                              void* d_out, int out_size) {
    const float* event = (const float*)d_in[0];
    const float* W[12];
    const float* Bv[12];
    for (int i = 0; i < 12; i++) {
        W[i] = (const float*)d_in[1 + 2 * i];
        Bv[i] = (const float*)d_in[2 + 2 * i];
    }
    // 0 neighbor, 1 pro_key, 2 pro_val, 3 lat_key, 4 lat_val, 5 tmp1,
    // 6 now1, 7 now_key, 8 now_val, 9 q, 10 k, 11 v

    float *nowval, *bc1, *bc2;
    bf16 *qb, *kb, *vb;
    bf16 *wb1, *wb2, *wbt, *wbnk, *wbq, *wbk, *wbv, *w8hi, *w8lo;
    cudaGetSymbolAddress((void**)&nowval, g_nowval);
    cudaGetSymbolAddress((void**)&qb, g_qb);
    cudaGetSymbolAddress((void**)&kb, g_kb);
    cudaGetSymbolAddress((void**)&vb, g_vb);
    cudaGetSymbolAddress((void**)&wb1, g_wb1);
    cudaGetSymbolAddress((void**)&wb2, g_wb2);
    cudaGetSymbolAddress((void**)&wbt, g_wbt);
    cudaGetSymbolAddress((void**)&wbnk, g_wbnk);
    cudaGetSymbolAddress((void**)&wbq, g_wbq);
    cudaGetSymbolAddress((void**)&wbk, g_wbk);
    cudaGetSymbolAddress((void**)&wbv, g_wbv);
    cudaGetSymbolAddress((void**)&w8hi, g_w8hi);
    cudaGetSymbolAddress((void**)&w8lo, g_w8lo);
    cudaGetSymbolAddress((void**)&bc1, g_bc1);
    cudaGetSymbolAddress((void**)&bc2, g_bc2);

    cudaFuncSetAttribute(attn_kernel, cudaFuncAttributeMaxDynamicSharedMemorySize, ATTN_SMEM);
    cudaFuncSetAttribute(gemm_nowval, cudaFuncAttributeMaxDynamicSharedMemorySize, NV_SMEM);
    cudaFuncSetAttribute(fused_conv_kernel, cudaFuncAttributeMaxDynamicSharedMemorySize, FUSED_SMEM);

    prep_w_kernel<<<640, 256>>>(W[1], W[3], W[2], W[4], W[5], W[7], W[9], W[10], W[11], W[8],
                                Bv[1], Bv[3], Bv[2], Bv[4]);

    fused_conv_kernel<<<PIX / 128, 256, FUSED_SMEM>>>(
        event, W[0], Bv[0], W[6], Bv[6],
        wb1, bc1, wb2, bc2, wbt, Bv[5], wbnk, Bv[7],
        wbq, Bv[9], wbk, Bv[10], wbv, Bv[11],
        qb, kb, vb);

    gemm_nowval<<<PIX / 128, 256, NV_SMEM>>>(event, W[6], Bv[6], w8hi, w8lo, Bv[8], nowval);

    attn_kernel<<<dim3(NSEQ / 128, BSZ), 256, ATTN_SMEM>>>(qb, kb, vb, nowval, 128,
                                                           (float*)d_out);
}

// round 8
// speedup vs baseline: 10.2185x; 1.0498x over previous
#include <cuda_runtime.h>
#include <cuda_bf16.h>
#include <cstdint>

// Problem constants
#define PIX 16384        // B*H*W
#define NSEQ 4096        // H*W
#define BSZ 4
#define CH 128
#define THITA 1e-4f

typedef __nv_bfloat16 bf16;

// ---------------- scratch (device globals; no allocation allowed) -------------
__device__ float g_nowval[PIX * 128];
__device__ bf16 g_qb[PIX * 128];
__device__ bf16 g_kb[PIX * 128];
__device__ bf16 g_vb[PIX * 128];
// bf16 weights
__device__ bf16 g_wb1[256 * 128];   // [w_pro_key ; w_lat_key]
__device__ bf16 g_wb2[256 * 128];   // [w_pro_val ; w_lat_val]
__device__ bf16 g_wbt[128 * 256];   // w_tmp1
__device__ bf16 g_wbnk[128 * 128];  // w_now_key
__device__ bf16 g_wbq[128 * 128];
__device__ bf16 g_wbk[128 * 128];
__device__ bf16 g_wbv[128 * 128];
__device__ bf16 g_w8hi[128 * 128];  // w_now_val split hi
__device__ bf16 g_w8lo[128 * 128];  // w_now_val split lo
__device__ float g_bc1[256];
__device__ float g_bc2[256];

// ---------------- weight prep: fp32 -> bf16 (+ concats + now_val split) ------
__global__ void __launch_bounds__(256) prep_w_kernel(
    const float* __restrict__ wpk, const float* __restrict__ wlk,
    const float* __restrict__ wpv, const float* __restrict__ wlv,
    const float* __restrict__ wt,  const float* __restrict__ wnk,
    const float* __restrict__ wq,  const float* __restrict__ wk,
    const float* __restrict__ wv,  const float* __restrict__ wnv,
    const float* __restrict__ bpk, const float* __restrict__ blk,
    const float* __restrict__ bpv, const float* __restrict__ blv) {
    int i = blockIdx.x * blockDim.x + threadIdx.x;   // 0..163839
    if (i < 32768) {
        g_wb1[i] = __float2bfloat16(i < 16384 ? wpk[i] : wlk[i - 16384]);
        g_wb2[i] = __float2bfloat16(i < 16384 ? wpv[i] : wlv[i - 16384]);
        g_wbt[i] = __float2bfloat16(wt[i]);
    } else if (i < 49152) {
        int j = i - 32768;
        if (j < 16384) {
            g_wbnk[j] = __float2bfloat16(wnk[j]);
            float v = wnv[j];
            bf16 h = __float2bfloat16(v);
            g_w8hi[j] = h;
            g_w8lo[j] = __float2bfloat16(v - __bfloat162float(h));
        }
    } else if (i < 65536) {
        int j = i - 49152;
        g_wbq[j] = __float2bfloat16(wq[j]);
        g_wbk[j] = __float2bfloat16(wk[j]);
        g_wbv[j] = __float2bfloat16(wv[j]);
    }
    if (i < 256) {
        g_bc1[i] = i < 128 ? bpk[i] : blk[i - 128];
        g_bc2[i] = i < 128 ? bpv[i] : blv[i - 128];
    }
}

// ---------------- mma / ldmatrix helpers --------------------------------------
__device__ __forceinline__ void mma16816(float* c, const uint32_t* a, const uint32_t* b) {
    asm volatile(
        "mma.sync.aligned.m16n8k16.row.col.f32.bf16.bf16.f32 "
        "{%0,%1,%2,%3}, {%4,%5,%6,%7}, {%8,%9}, {%0,%1,%2,%3};"
        : "+f"(c[0]), "+f"(c[1]), "+f"(c[2]), "+f"(c[3])
        : "r"(a[0]), "r"(a[1]), "r"(a[2]), "r"(a[3]), "r"(b[0]), "r"(b[1]));
}

__device__ __forceinline__ void ldsm4(uint32_t& r0, uint32_t& r1, uint32_t& r2, uint32_t& r3,
                                      const void* p) {
    uint32_t addr = (uint32_t)__cvta_generic_to_shared(p);
    asm volatile("ldmatrix.sync.aligned.m8n8.x4.shared.b16 {%0,%1,%2,%3}, [%4];"
                 : "=r"(r0), "=r"(r1), "=r"(r2), "=r"(r3) : "r"(addr));
}

__device__ __forceinline__ void ldsm4t(uint32_t& r0, uint32_t& r1, uint32_t& r2, uint32_t& r3,
                                       const void* p) {
    uint32_t addr = (uint32_t)__cvta_generic_to_shared(p);
    asm volatile("ldmatrix.sync.aligned.m8n8.x4.trans.shared.b16 {%0,%1,%2,%3}, [%4];"
                 : "=r"(r0), "=r"(r1), "=r"(r2), "=r"(r3) : "r"(addr));
}

__device__ __forceinline__ uint32_t packbf2(float lo, float hi) {
    uint32_t d;
    asm("cvt.rn.bf16x2.f32 %0, %1, %2;" : "=r"(d) : "f"(hi), "f"(lo));
    return d;
}

__device__ __forceinline__ void cpasync16(void* dst, const void* src) {
    uint32_t d = (uint32_t)__cvta_generic_to_shared(dst);
    asm volatile("cp.async.cg.shared.global [%0], [%1], 16;" :: "r"(d), "l"(src));
}
#define CP_COMMIT() asm volatile("cp.async.commit_group;")
#define CP_WAIT0()  asm volatile("cp.async.wait_group 0;")
#define CP_WAIT1()  asm volatile("cp.async.wait_group 1;")

// ============ fused conv chain =================================================
template <int K>
__device__ __forceinline__ void stage_gemm(
    const bf16* __restrict__ inb,
    const bf16* __restrict__ wg,
    const float* __restrict__ bias,
    bf16* __restrict__ wbuf,
    bf16* __restrict__ outb,
    bf16* __restrict__ outg,
    int m0, int tid) {
    const int lane = tid & 31, wid = tid >> 5;
    const int wm = (wid & 1) * 64, wn = (wid >> 1) * 32;
    const int g = lane >> 2, tc = lane & 3;
    const int rA_loc = ((lane >> 3) & 1) * 8 + (lane & 7);
    const int cA_bit = (lane >> 4) & 1;
    const int rB_loc = ((lane >> 4) & 1) * 8 + (lane & 7);
    const int cB_bit = (lane >> 3) & 1;
    constexpr int CPR = K >> 3;

#pragma unroll
    for (int i = tid; i < 128 * CPR; i += 256) {
        int n = i / CPR, ck = i % CPR;
        int kb = ck >> 3, c8 = ck & 7;
        cpasync16((uint4*)wbuf + kb * 1024 + n * 8 + (c8 ^ (n & 7)),
                  (const uint4*)wg + i);
    }
    CP_COMMIT();
    CP_WAIT0();
    __syncthreads();

    float acc[4][4][4];
#pragma unroll
    for (int i = 0; i < 4; i++)
#pragma unroll
        for (int j = 0; j < 4; j++)
#pragma unroll
            for (int l = 0; l < 4; l++) acc[i][j][l] = 0.f;

#pragma unroll
    for (int kb = 0; kb < K / 64; kb++) {
        const bf16* As = inb + kb * 8192;
        const bf16* Bs = wbuf + kb * 8192;
#pragma unroll
        for (int ks = 0; ks < 4; ks++) {
            uint32_t a[4][4], bf[2][4];
#pragma unroll
            for (int mi = 0; mi < 4; mi++) {
                int r = wm + mi * 16 + rA_loc;
                int ch = 2 * ks + cA_bit;
                ldsm4(a[mi][0], a[mi][1], a[mi][2], a[mi][3],
                      As + r * 64 + ((ch ^ (r & 7)) << 3));
            }
#pragma unroll
            for (int ni = 0; ni < 2; ni++) {
                int r = wn + ni * 16 + rB_loc;
                int ch = 2 * ks + cB_bit;
                ldsm4(bf[ni][0], bf[ni][1], bf[ni][2], bf[ni][3],
                      Bs + r * 64 + ((ch ^ (r & 7)) << 3));
            }
#pragma unroll
            for (int mi = 0; mi < 4; mi++)
#pragma unroll
                for (int ni = 0; ni < 2; ni++) {
                    uint32_t b0[2] = {bf[ni][0], bf[ni][1]};
                    mma16816(acc[mi][2 * ni], a[mi], b0);
                    uint32_t b1[2] = {bf[ni][2], bf[ni][3]};
                    mma16816(acc[mi][2 * ni + 1], a[mi], b1);
                }
        }
    }

#pragma unroll
    for (int mi = 0; mi < 4; mi++) {
        int r0 = wm + mi * 16 + g;
#pragma unroll
        for (int n8 = 0; n8 < 4; n8++) {
            int c = wn + n8 * 8 + 2 * tc;
            float2 bv = *(const float2*)(bias + c);
            uint32_t p0 = packbf2(fmaxf(acc[mi][n8][0] + bv.x, 0.f),
                                  fmaxf(acc[mi][n8][1] + bv.y, 0.f));
            uint32_t p1 = packbf2(fmaxf(acc[mi][n8][2] + bv.x, 0.f),
                                  fmaxf(acc[mi][n8][3] + bv.y, 0.f));
            if (outb) {
                int kb_o = c >> 6, cl = c & 63, chk = cl >> 3, off = cl & 7;
                bf16* base = outb + kb_o * 8192;
                *(uint32_t*)(base + r0 * 64 + ((chk ^ (r0 & 7)) << 3) + off) = p0;
                int r1 = r0 + 8;
                *(uint32_t*)(base + r1 * 64 + ((chk ^ (r1 & 7)) << 3) + off) = p1;
            } else {
                *(uint32_t*)(outg + (size_t)(m0 + r0) * 128 + c) = p0;
                *(uint32_t*)(outg + (size_t)(m0 + r0 + 8) * 128 + c) = p1;
            }
        }
    }
    __syncthreads();
}

#define FUSED_SMEM (65536 + 65536 + 32768 + 65536)   // A,B,C,W = 229376 B

__global__ void __launch_bounds__(256, 1) fused_conv_kernel(
    const float* __restrict__ event,
    const float* __restrict__ w0, const float* __restrict__ b0,
    const float* __restrict__ w6, const float* __restrict__ b6,
    const bf16* __restrict__ wb1, const float* __restrict__ bc1,
    const bf16* __restrict__ wb2, const float* __restrict__ bc2,
    const bf16* __restrict__ wbt, const float* __restrict__ bt,
    const bf16* __restrict__ wbnk, const float* __restrict__ bnk,
    const bf16* __restrict__ wbq, const float* __restrict__ bq,
    const bf16* __restrict__ wbk, const float* __restrict__ bk,
    const bf16* __restrict__ wbv, const float* __restrict__ bv,
    bf16* __restrict__ qb, bf16* __restrict__ kb_, bf16* __restrict__ vb) {
    extern __shared__ char sm[];
    bf16* A = (bf16*)sm;
    bf16* B = (bf16*)(sm + 65536);
    bf16* C = (bf16*)(sm + 131072);
    bf16* W = (bf16*)(sm + 163840);
    const int tid = threadIdx.x;
    const int m0 = blockIdx.x * 128;
    const float* ev = event + (size_t)(m0 >> 12) * 6 * NSEQ + (m0 & 4095);

    for (int i = tid; i < 4096; i += 256) {
        int r = i >> 5, ck = i & 31;
        float x0 = ev[r], x1 = ev[NSEQ + r], x2 = ev[4 * NSEQ + r], x3 = ev[5 * NSEQ + r];
        uint32_t pk[4];
#pragma unroll
        for (int j = 0; j < 4; j++) {
            int c0 = ck * 8 + 2 * j, c1 = c0 + 1;
            float v0 = fmaf(w0[c0 * 4 + 3], x3, fmaf(w0[c0 * 4 + 2], x2,
                       fmaf(w0[c0 * 4 + 1], x1, fmaf(w0[c0 * 4], x0, b0[c0]))));
            float v1 = fmaf(w0[c1 * 4 + 3], x3, fmaf(w0[c1 * 4 + 2], x2,
                       fmaf(w0[c1 * 4 + 1], x1, fmaf(w0[c1 * 4], x0, b0[c1]))));
            pk[j] = packbf2(fmaxf(v0, 0.f), fmaxf(v1, 0.f));
        }
        ((uint4*)A)[(ck >> 3) * 1024 + r * 8 + ((ck & 7) ^ (r & 7))] =
            make_uint4(pk[0], pk[1], pk[2], pk[3]);
    }
    __syncthreads();

    stage_gemm<128>(A, wb1, bc1, W, B, nullptr, m0, tid);
    stage_gemm<128>(A, wb1 + 128 * 128, bc1 + 128, W, B + 2 * 8192, nullptr, m0, tid);
    stage_gemm<256>(B, wbt, bt, W, C, nullptr, m0, tid);
    stage_gemm<128>(C, wbq, bq, W, nullptr, qb, m0, tid);

    stage_gemm<128>(A + 2 * 8192, wb2, bc2, W, B, nullptr, m0, tid);
    stage_gemm<128>(A + 2 * 8192, wb2 + 128 * 128, bc2 + 128, W, B + 2 * 8192, nullptr, m0, tid);
    stage_gemm<256>(B, wbt, bt, W, C, nullptr, m0, tid);
    stage_gemm<128>(C, wbv, bv, W, nullptr, vb, m0, tid);

    for (int i = tid; i < 2048; i += 256) {
        int r = i >> 4, ck = i & 15;
        float x = ev[2 * NSEQ + r], y = ev[3 * NSEQ + r];
        uint32_t pk[4];
#pragma unroll
        for (int j = 0; j < 4; j++) {
            int c0 = ck * 8 + 2 * j, c1 = c0 + 1;
            float v0 = fmaxf(fmaf(w6[c0 * 2 + 1], y, fmaf(w6[c0 * 2], x, b6[c0])), 0.f);
            float v1 = fmaxf(fmaf(w6[c1 * 2 + 1], y, fmaf(w6[c1 * 2], x, b6[c1])), 0.f);
            pk[j] = packbf2(v0, v1);
        }
        ((uint4*)A)[(ck >> 3) * 1024 + r * 8 + ((ck & 7) ^ (r & 7))] =
            make_uint4(pk[0], pk[1], pk[2], pk[3]);
    }
    __syncthreads();
    stage_gemm<128>(A, wbnk, bnk, W, C, nullptr, m0, tid);
    stage_gemm<128>(C, wbk, bk, W, nullptr, kb_, m0, tid);
}

// ---------------- now_val: fused nowf + split-bf16 GEMM -----------------------
#define NV_SMEM (65536 + 1024 + 1024 + 512)

__global__ void __launch_bounds__(256) gemm_nowval(
    const float* __restrict__ event,
    const float* __restrict__ w6, const float* __restrict__ b6,
    const bf16* __restrict__ w8hi, const bf16* __restrict__ w8lo,
    const float* __restrict__ b8,
    float* __restrict__ out) {
    extern __shared__ char sm[];
    bf16* Ah = (bf16*)sm;
    bf16* Al = Ah + 128 * 64;
    bf16* Bh = Al + 128 * 64;
    bf16* Bl = Bh + 128 * 64;
    float* x2s = (float*)(sm + 65536);
    float* w6s = x2s + 256;
    float* b6s = w6s + 256;

    const int tid = threadIdx.x, lane = tid & 31, wid = tid >> 5;
    const int m0 = blockIdx.x * 128;
    const int wm = (wid & 1) * 64, wn = (wid >> 1) * 32;
    const int g = lane >> 2, tc = lane & 3;
    const int rA_loc = ((lane >> 3) & 1) * 8 + (lane & 7);
    const int cA_bit = (lane >> 4) & 1;
    const int rB_loc = ((lane >> 4) & 1) * 8 + (lane & 7);
    const int cB_bit = (lane >> 3) & 1;

    {
        int bb = m0 >> 12;
        const float* e = event + (size_t)bb * 6 * NSEQ + (m0 & 4095);
        if (tid < 128) {
            x2s[2 * tid] = e[2 * NSEQ + tid];
            x2s[2 * tid + 1] = e[3 * NSEQ + tid];
            b6s[tid] = b6[tid];
        } else {
            int j = tid - 128;
            ((float2*)w6s)[j] = ((const float2*)w6)[j];
        }
    }
    __syncthreads();

    float acc[4][4][4];
#pragma unroll
    for (int i = 0; i < 4; i++)
#pragma unroll
        for (int j = 0; j < 4; j++)
#pragma unroll
            for (int l = 0; l < 4; l++) acc[i][j][l] = 0.f;

    for (int k0 = 0; k0 < 128; k0 += 64) {
#pragma unroll
        for (int i = 0; i < 4; i++) {
            int li = tid + i * 256;
            int r = li >> 3, cch = li & 7;
            float x0 = x2s[2 * r], x1 = x2s[2 * r + 1];
            uint4 hq, lq;
            bf16* hp = (bf16*)&hq;
            bf16* lp = (bf16*)&lq;
#pragma unroll
            for (int j = 0; j < 8; j++) {
                int k = k0 + cch * 8 + j;
                float v = fmaxf(fmaf(w6s[2 * k + 1], x1, fmaf(w6s[2 * k], x0, b6s[k])), 0.f);
                bf16 h = __float2bfloat16(v);
                hp[j] = h;
                lp[j] = __float2bfloat16(v - __bfloat162float(h));
            }
            int sidx = r * 8 + (cch ^ (r & 7));
            ((uint4*)Ah)[sidx] = hq;
            ((uint4*)Al)[sidx] = lq;
            ((uint4*)Bh)[sidx] = *(const uint4*)(w8hi + (size_t)r * 128 + k0 + cch * 8);
            ((uint4*)Bl)[sidx] = *(const uint4*)(w8lo + (size_t)r * 128 + k0 + cch * 8);
        }
        __syncthreads();
#pragma unroll
        for (int ks = 0; ks < 4; ks++) {
            uint32_t ah[4][4], al[4][4], bh[2][4], bl[2][4];
#pragma unroll
            for (int mi = 0; mi < 4; mi++) {
                int r = wm + mi * 16 + rA_loc;
                int ch = 2 * ks + cA_bit;
                int off = r * 64 + ((ch ^ (r & 7)) << 3);
                ldsm4(ah[mi][0], ah[mi][1], ah[mi][2], ah[mi][3], Ah + off);
                ldsm4(al[mi][0], al[mi][1], al[mi][2], al[mi][3], Al + off);
            }
#pragma unroll
            for (int ni = 0; ni < 2; ni++) {
                int r = wn + ni * 16 + rB_loc;
                int ch = 2 * ks + cB_bit;
                int off = r * 64 + ((ch ^ (r & 7)) << 3);
                ldsm4(bh[ni][0], bh[ni][1], bh[ni][2], bh[ni][3], Bh + off);
                ldsm4(bl[ni][0], bl[ni][1], bl[ni][2], bl[ni][3], Bl + off);
            }
#pragma unroll
            for (int mi = 0; mi < 4; mi++)
#pragma unroll
                for (int ni = 0; ni < 2; ni++) {
                    uint32_t h0[2] = {bh[ni][0], bh[ni][1]};
                    uint32_t h1[2] = {bh[ni][2], bh[ni][3]};
                    uint32_t l0[2] = {bl[ni][0], bl[ni][1]};
                    uint32_t l1[2] = {bl[ni][2], bl[ni][3]};
                    mma16816(acc[mi][2 * ni], ah[mi], h0);
                    mma16816(acc[mi][2 * ni + 1], ah[mi], h1);
                    mma16816(acc[mi][2 * ni], ah[mi], l0);
                    mma16816(acc[mi][2 * ni + 1], ah[mi], l1);
                    mma16816(acc[mi][2 * ni], al[mi], h0);
                    mma16816(acc[mi][2 * ni + 1], al[mi], h1);
                }
        }
        __syncthreads();
    }
#pragma unroll
    for (int mi = 0; mi < 4; mi++) {
        int r0 = m0 + wm + mi * 16 + g;
#pragma unroll
        for (int n8 = 0; n8 < 4; n8++) {
            int c = wn + n8 * 8 + 2 * tc;
            float2 bv = *(const float2*)(b8 + c);
            float2 v01, v23;
            v01.x = fmaxf(acc[mi][n8][0] + bv.x, 0.f);
            v01.y = fmaxf(acc[mi][n8][1] + bv.y, 0.f);
            v23.x = fmaxf(acc[mi][n8][2] + bv.x, 0.f);
            v23.y = fmaxf(acc[mi][n8][3] + bv.y, 0.f);
            *(float2*)(out + (size_t)r0 * 128 + c) = v01;
            *(float2*)(out + (size_t)(r0 + 8) * 128 + c) = v23;
        }
    }
}

// ---------------- fast exp (Schraudolph); args <= 0, clamp avoids wraparound --
__device__ __forceinline__ float fast_exp(float x) {
    x = fmaxf(x, -80.f);
    int i = (int)(fmaf(x, 12102203.0f, 1064866805.0f));
    return __int_as_float(i);
}

// ---------------- flash attention, bf16 HMMA, BM=128 BN=128, 2-stage cp.async -
#define OPITCH 132
#define ATTN_SMEM 131072   // 2 stages * (32KB K + 32KB V)

__global__ void __launch_bounds__(256, 1) attn_kernel(
    const bf16* __restrict__ gq,
    const bf16* __restrict__ gk,
    const bf16* __restrict__ gv,
    const float* __restrict__ gnv, int nv_ld,
    float* __restrict__ out) {
    extern __shared__ char smraw[];
    float* OutS = (float*)smraw;                   // reused post-loop, [128][OPITCH]

    const int tid = threadIdx.x;
    const int lane = tid & 31, w = tid >> 5;
    const int g = lane >> 2, tc = lane & 3;
    const int b = blockIdx.y;
    const int q0 = blockIdx.x * 128;

    uint32_t qa[8][4];
    {
        const bf16* Qb = gq + ((size_t)(b * NSEQ) + q0 + w * 16) * CH;
#pragma unroll
        for (int kb = 0; kb < 8; kb++) {
            qa[kb][0] = *(const uint32_t*)(Qb + (size_t)g * CH + kb * 16 + 2 * tc);
            qa[kb][1] = *(const uint32_t*)(Qb + (size_t)(g + 8) * CH + kb * 16 + 2 * tc);
            qa[kb][2] = *(const uint32_t*)(Qb + (size_t)g * CH + kb * 16 + 8 + 2 * tc);
            qa[kb][3] = *(const uint32_t*)(Qb + (size_t)(g + 8) * CH + kb * 16 + 8 + 2 * tc);
        }
    }

    float O[16][4];
#pragma unroll
    for (int i = 0; i < 16; i++)
#pragma unroll
        for (int j = 0; j < 4; j++) O[i][j] = 0.f;
    float mrow0 = -1e30f, mrow1 = -1e30f, lrow0 = 0.f, lrow1 = 0.f;

    const int rK_loc = ((lane >> 4) & 1) * 8 + (lane & 7);
    const int cK_bit = (lane >> 3) & 1;
    const int rV_loc = ((lane >> 3) & 1) * 8 + (lane & 7);
    const int cV_bit = lane >> 4;

    const bf16* Kgb = gk + (size_t)b * NSEQ * CH;
    const bf16* Vgb = gv + (size_t)b * NSEQ * CH;

    // stage tile jt (128 K rows + 128 V rows) into buffer s via cp.async
    auto stage = [&](int jt, int s) {
        const uint4* Kg = (const uint4*)(Kgb + (size_t)jt * 128 * CH);
        const uint4* Vg = (const uint4*)(Vgb + (size_t)jt * 128 * CH);
        uint4* Kd = (uint4*)(smraw + s * 65536);
        uint4* Vd = Kd + 2048;
#pragma unroll
        for (int i = tid; i < 2048; i += 256) {
            int r = i >> 4, ch = i & 15, sch = ch ^ (r & 7);
            cpasync16(Kd + r * 16 + sch, Kg + i);
            cpasync16(Vd + r * 16 + sch, Vg + i);
        }
    };

    stage(0, 0);
    CP_COMMIT();

    for (int jt = 0; jt < NSEQ / 128; jt++) {
        if (jt + 1 < NSEQ / 128) stage(jt + 1, (jt + 1) & 1);
        CP_COMMIT();
        CP_WAIT1();
        __syncthreads();

        bf16* Ks = (bf16*)(smraw + (jt & 1) * 65536);
        bf16* Vs = Ks + 128 * 128;

        // ---- S = Q K^T  (16 x 128 per warp) ----
        float S[16][4];
#pragma unroll
        for (int i = 0; i < 16; i++)
#pragma unroll
            for (int j = 0; j < 4; j++) S[i][j] = 0.f;
#pragma unroll
        for (int kb = 0; kb < 8; kb++) {
#pragma unroll
            for (int p = 0; p < 8; p++) {
                int r = p * 16 + rK_loc;
                int ch = 2 * kb + cK_bit;
                uint32_t b0, b1, b2, b3;
                ldsm4(b0, b1, b2, b3, Ks + r * 128 + ((ch ^ (r & 7)) << 3));
                uint32_t bb[2] = {b0, b1};
                mma16816(S[2 * p], qa[kb], bb);
                uint32_t bb2[2] = {b2, b3};
                mma16816(S[2 * p + 1], qa[kb], bb2);
            }
        }

        // ---- online softmax ----
        float m0 = -1e30f, m1 = -1e30f;
#pragma unroll
        for (int nb = 0; nb < 16; nb++) {
            m0 = fmaxf(m0, fmaxf(S[nb][0], S[nb][1]));
            m1 = fmaxf(m1, fmaxf(S[nb][2], S[nb][3]));
        }
        m0 = fmaxf(m0, __shfl_xor_sync(0xffffffffu, m0, 1));
        m0 = fmaxf(m0, __shfl_xor_sync(0xffffffffu, m0, 2));
        m1 = fmaxf(m1, __shfl_xor_sync(0xffffffffu, m1, 1));
        m1 = fmaxf(m1, __shfl_xor_sync(0xffffffffu, m1, 2));
        float mn0 = fmaxf(mrow0, m0), mn1 = fmaxf(mrow1, m1);
        bool inc = (mn0 > mrow0) | (mn1 > mrow1);
        if (__any_sync(0xffffffffu, inc)) {
            float scl0 = fast_exp(mrow0 - mn0), scl1 = fast_exp(mrow1 - mn1);
            lrow0 *= scl0; lrow1 *= scl1;
#pragma unroll
            for (int nb = 0; nb < 16; nb++) {
                O[nb][0] *= scl0; O[nb][1] *= scl0;
                O[nb][2] *= scl1; O[nb][3] *= scl1;
            }
        }
        mrow0 = mn0; mrow1 = mn1;
        float rs0 = 0.f, rs1 = 0.f;
#pragma unroll
        for (int nb = 0; nb < 16; nb++) {
            S[nb][0] = fast_exp(S[nb][0] - mn0);
            S[nb][1] = fast_exp(S[nb][1] - mn0);
            S[nb][2] = fast_exp(S[nb][2] - mn1);
            S[nb][3] = fast_exp(S[nb][3] - mn1);
            rs0 += S[nb][0] + S[nb][1];
            rs1 += S[nb][2] + S[nb][3];
        }
        rs0 += __shfl_xor_sync(0xffffffffu, rs0, 1);
        rs0 += __shfl_xor_sync(0xffffffffu, rs0, 2);
        rs1 += __shfl_xor_sync(0xffffffffu, rs1, 1);
        rs1 += __shfl_xor_sync(0xffffffffu, rs1, 2);
        lrow0 += rs0;
        lrow1 += rs1;

        // ---- P fragments (C->A layout identity) ----
        uint32_t pa[8][4];
#pragma unroll
        for (int jb = 0; jb < 8; jb++) {
            pa[jb][0] = packbf2(S[2 * jb][0], S[2 * jb][1]);
            pa[jb][1] = packbf2(S[2 * jb][2], S[2 * jb][3]);
            pa[jb][2] = packbf2(S[2 * jb + 1][0], S[2 * jb + 1][1]);
            pa[jb][3] = packbf2(S[2 * jb + 1][2], S[2 * jb + 1][3]);
        }

        // ---- O += P V ----
#pragma unroll
        for (int jb = 0; jb < 8; jb++) {
            int r = jb * 16 + rV_loc;
#pragma unroll
            for (int cp = 0; cp < 8; cp++) {
                int ch = 2 * cp + cV_bit;
                uint32_t b0, b1, b2, b3;
                ldsm4t(b0, b1, b2, b3, Vs + r * 128 + ((ch ^ (r & 7)) << 3));
                uint32_t bb[2] = {b0, b1};
                mma16816(O[2 * cp], pa[jb], bb);
                uint32_t bb2[2] = {b2, b3};
                mma16816(O[2 * cp + 1], pa[jb], bb2);
            }
        }
        __syncthreads();
    }

    // ---- epilogue ----
    {
        float inv0 = 1.f / lrow0, inv1 = 1.f / lrow1;
        int row0 = w * 16 + g, row1 = row0 + 8;
        const float* nvp0 = gnv + ((size_t)(b * NSEQ) + q0 + row0) * nv_ld;
        const float* nvp1 = gnv + ((size_t)(b * NSEQ) + q0 + row1) * nv_ld;
#pragma unroll
        for (int nb = 0; nb < 16; nb++) {
            int c = nb * 8 + 2 * tc;
            float2 nv0 = *(const float2*)(nvp0 + c);
            float2 nv1 = *(const float2*)(nvp1 + c);
            OutS[c * OPITCH + row0] = fmaf(THITA, O[nb][0] * inv0, nv0.x);
            OutS[(c + 1) * OPITCH + row0] = fmaf(THITA, O[nb][1] * inv0, nv0.y);
            OutS[c * OPITCH + row1] = fmaf(THITA, O[nb][2] * inv1, nv1.x);
            OutS[(c + 1) * OPITCH + row1] = fmaf(THITA, O[nb][3] * inv1, nv1.y);
        }
    }
    __syncthreads();
    {
        float* ob = out + (size_t)b * CH * NSEQ + q0;
        for (int i = tid; i < 128 * 128 / 4; i += 256) {
            int idx = i * 4;
            int c = idx >> 7, nl = idx & 127;
            float4 v = *(const float4*)(OutS + c * OPITCH + nl);
            *(float4*)(ob + (size_t)c * NSEQ + nl) = v;
        }
    }
}

// ---------------- host launch --------------------------------------------------
extern "C" void kernel_launch(void* const* d_in, const int* in_sizes, int n_in,
                              void* d_out, int out_size) {
    const float* event = (const float*)d_in[0];
    const float* W[12];
    const float* Bv[12];
    for (int i = 0; i < 12; i++) {
        W[i] = (const float*)d_in[1 + 2 * i];
        Bv[i] = (const float*)d_in[2 + 2 * i];
    }

    float *nowval, *bc1, *bc2;
    bf16 *qb, *kb, *vb;
    bf16 *wb1, *wb2, *wbt, *wbnk, *wbq, *wbk, *wbv, *w8hi, *w8lo;
    cudaGetSymbolAddress((void**)&nowval, g_nowval);
    cudaGetSymbolAddress((void**)&qb, g_qb);
    cudaGetSymbolAddress((void**)&kb, g_kb);
    cudaGetSymbolAddress((void**)&vb, g_vb);
    cudaGetSymbolAddress((void**)&wb1, g_wb1);
    cudaGetSymbolAddress((void**)&wb2, g_wb2);
    cudaGetSymbolAddress((void**)&wbt, g_wbt);
    cudaGetSymbolAddress((void**)&wbnk, g_wbnk);
    cudaGetSymbolAddress((void**)&wbq, g_wbq);
    cudaGetSymbolAddress((void**)&wbk, g_wbk);
    cudaGetSymbolAddress((void**)&wbv, g_wbv);
    cudaGetSymbolAddress((void**)&w8hi, g_w8hi);
    cudaGetSymbolAddress((void**)&w8lo, g_w8lo);
    cudaGetSymbolAddress((void**)&bc1, g_bc1);
    cudaGetSymbolAddress((void**)&bc2, g_bc2);

    cudaFuncSetAttribute(attn_kernel, cudaFuncAttributeMaxDynamicSharedMemorySize, ATTN_SMEM);
    cudaFuncSetAttribute(gemm_nowval, cudaFuncAttributeMaxDynamicSharedMemorySize, NV_SMEM);
    cudaFuncSetAttribute(fused_conv_kernel, cudaFuncAttributeMaxDynamicSharedMemorySize, FUSED_SMEM);

    prep_w_kernel<<<640, 256>>>(W[1], W[3], W[2], W[4], W[5], W[7], W[9], W[10], W[11], W[8],
                                Bv[1], Bv[3], Bv[2], Bv[4]);

    fused_conv_kernel<<<PIX / 128, 256, FUSED_SMEM>>>(
        event, W[0], Bv[0], W[6], Bv[6],
        wb1, bc1, wb2, bc2, wbt, Bv[5], wbnk, Bv[7],
        wbq, Bv[9], wbk, Bv[10], wbv, Bv[11],
        qb, kb, vb);

    gemm_nowval<<<PIX / 128, 256, NV_SMEM>>>(event, W[6], Bv[6], w8hi, w8lo, Bv[8], nowval);

    attn_kernel<<<dim3(NSEQ / 128, BSZ), 256, ATTN_SMEM>>>(qb, kb, vb, nowval, 128,
                                                           (float*)d_out);
}